// round 4
// baseline (speedup 1.0000x reference)
#include <cuda_runtime.h>
#include <math.h>

// Problem constants
#define B_SZ   4
#define S_LEN  2048
#define D_DIM  1024
#define H_NUM  16
#define DKH    64
#define M_TOT  (B_SZ * S_LEN)     // 8192
#define K_TOT  D_DIM              // 1024
#define N_TOT  D_DIM              // 1024

// Scratch: Q,K,V in [B,H,S,DK] head-major layout; O in [B,S,D]
__device__ float g_Q[B_SZ * H_NUM * S_LEN * DKH];
__device__ float g_K[B_SZ * H_NUM * S_LEN * DKH];
__device__ float g_V[B_SZ * H_NUM * S_LEN * DKH];
__device__ float g_O[M_TOT * D_DIM];

// ---------------------------------------------------------------------------
// SGEMM core: C[M,N] = A[M,K] @ W[N,K]^T  (both operands K-contiguous, "NT")
// M=8192, N=1024, K=1024. BM=BN=128, BK=8, 256 threads, 8x8 per thread.
// Double-buffered shared memory: one __syncthreads per k-tile, global
// prefetch overlapped with compute.
// ---------------------------------------------------------------------------
#define GEMM_BUF 1024   // 8 * 128 floats per buffer

__device__ __forceinline__ void gemm_core(const float* __restrict__ A,
                                          const float* __restrict__ W,
                                          float (&acc)[8][8],
                                          float* __restrict__ As,
                                          float* __restrict__ Bs)
{
    const int tid = threadIdx.x;
    const int lr  = tid >> 1;          // 0..127 tile row for loading
    const int lk  = (tid & 1) << 2;    // 0 or 4 (k offset of the float4)
    const int tr  = tid >> 4;          // 0..15: compute row group
    const int tc  = tid & 15;          // 0..15: compute col group

    const float* Ap = A + ((size_t)blockIdx.x * 128 + lr) * K_TOT + lk;
    const float* Wp = W + ((size_t)blockIdx.y * 128 + lr) * K_TOT + lk;

    // Preload k-tile 0 into buffer 0
    float4 av = *(const float4*)(Ap);
    float4 bv = *(const float4*)(Wp);
    As[(lk + 0) * 128 + lr] = av.x;
    As[(lk + 1) * 128 + lr] = av.y;
    As[(lk + 2) * 128 + lr] = av.z;
    As[(lk + 3) * 128 + lr] = av.w;
    Bs[(lk + 0) * 128 + lr] = bv.x;
    Bs[(lk + 1) * 128 + lr] = bv.y;
    Bs[(lk + 2) * 128 + lr] = bv.z;
    Bs[(lk + 3) * 128 + lr] = bv.w;
    __syncthreads();

    int buf = 0;
    #pragma unroll 1
    for (int k0 = 0; k0 < K_TOT; k0 += 8) {
        // Prefetch next k-tile from global while computing current one
        const bool has_next = (k0 + 8 < K_TOT);
        if (has_next) {
            av = *(const float4*)(Ap + k0 + 8);
            bv = *(const float4*)(Wp + k0 + 8);
        }

        const float* Asb = As + buf * GEMM_BUF;
        const float* Bsb = Bs + buf * GEMM_BUF;
        #pragma unroll
        for (int kk = 0; kk < 8; kk++) {
            float4 a0 = *(const float4*)&Asb[kk * 128 + tr * 8];
            float4 a1 = *(const float4*)&Asb[kk * 128 + tr * 8 + 4];
            float4 b0 = *(const float4*)&Bsb[kk * 128 + tc * 8];
            float4 b1 = *(const float4*)&Bsb[kk * 128 + tc * 8 + 4];
            float ra[8] = {a0.x, a0.y, a0.z, a0.w, a1.x, a1.y, a1.z, a1.w};
            float rb[8] = {b0.x, b0.y, b0.z, b0.w, b1.x, b1.y, b1.z, b1.w};
            #pragma unroll
            for (int i = 0; i < 8; i++)
                #pragma unroll
                for (int j = 0; j < 8; j++)
                    acc[i][j] = fmaf(ra[i], rb[j], acc[i][j]);
        }

        if (has_next) {
            float* Asw = As + (buf ^ 1) * GEMM_BUF;
            float* Bsw = Bs + (buf ^ 1) * GEMM_BUF;
            Asw[(lk + 0) * 128 + lr] = av.x;
            Asw[(lk + 1) * 128 + lr] = av.y;
            Asw[(lk + 2) * 128 + lr] = av.z;
            Asw[(lk + 3) * 128 + lr] = av.w;
            Bsw[(lk + 0) * 128 + lr] = bv.x;
            Bsw[(lk + 1) * 128 + lr] = bv.y;
            Bsw[(lk + 2) * 128 + lr] = bv.z;
            Bsw[(lk + 3) * 128 + lr] = bv.w;
            __syncthreads();
            buf ^= 1;
        }
    }
}

// QKV projection: z selects (Wq->g_Q, Wk->g_K, Wv->g_V); writes [B,H,S,DK]
__global__ __launch_bounds__(256) void qkv_kernel(const float* __restrict__ x,
                                                  const float* __restrict__ Wq,
                                                  const float* __restrict__ Wk,
                                                  const float* __restrict__ Wv)
{
    __shared__ float As[2 * GEMM_BUF];
    __shared__ float Bs[2 * GEMM_BUF];
    const float* W = (blockIdx.z == 0) ? Wq : (blockIdx.z == 1) ? Wk : Wv;
    float* out     = (blockIdx.z == 0) ? g_Q : (blockIdx.z == 1) ? g_K : g_V;

    float acc[8][8];
    #pragma unroll
    for (int i = 0; i < 8; i++)
        #pragma unroll
        for (int j = 0; j < 8; j++) acc[i][j] = 0.0f;

    gemm_core(x, W, acc, As, Bs);

    const int tr = threadIdx.x >> 4;
    const int tc = threadIdx.x & 15;
    #pragma unroll
    for (int i = 0; i < 8; i++) {
        int m = blockIdx.x * 128 + tr * 8 + i;   // b*S + s
        int b = m >> 11;                         // /2048
        int s = m & 2047;
        #pragma unroll
        for (int j = 0; j < 8; j++) {
            int n  = blockIdx.y * 128 + tc * 8 + j;  // h*64 + dk
            int h  = n >> 6;
            int dk = n & 63;
            out[((((b << 4) + h) * S_LEN) + s) * DKH + dk] = acc[i][j];
        }
    }
}

// Output projection: d_out[m,n] = sum_k g_O[m,k] * Wo[n,k]
__global__ __launch_bounds__(256) void proj_kernel(const float* __restrict__ Wo,
                                                   float* __restrict__ C)
{
    __shared__ float As[2 * GEMM_BUF];
    __shared__ float Bs[2 * GEMM_BUF];
    float acc[8][8];
    #pragma unroll
    for (int i = 0; i < 8; i++)
        #pragma unroll
        for (int j = 0; j < 8; j++) acc[i][j] = 0.0f;

    gemm_core(g_O, Wo, acc, As, Bs);

    const int tr = threadIdx.x >> 4;
    const int tc = threadIdx.x & 15;
    #pragma unroll
    for (int i = 0; i < 8; i++) {
        int m = blockIdx.x * 128 + tr * 8 + i;
        #pragma unroll
        for (int j = 0; j < 8; j++) {
            int n = blockIdx.y * 128 + tc * 8 + j;
            C[(size_t)m * N_TOT + n] = acc[i][j];
        }
    }
}

// ---------------------------------------------------------------------------
// Flash attention: per (b,h), Q[2048,64] x K[2048,64]^T -> softmax -> x V
// Block: 64 query rows, loops over 32 key tiles of 64. 256 threads (16x16).
// Thread (ty,tx): scores for q-rows ty*4+i, keys j*16+tx; output cols tx*4+j.
// ---------------------------------------------------------------------------
#define KS_STRIDE 68
#define ATTN_SMEM ((64 * 64 + 3 * 64 * KS_STRIDE) * 4)

__global__ __launch_bounds__(256) void attn_kernel(float* __restrict__ O)
{
    extern __shared__ float sm[];
    float* Qs = sm;                     // 64*64
    float* Ks = Qs + 64 * 64;           // 64*68
    float* Vs = Ks + 64 * KS_STRIDE;    // 64*68
    float* Ps = Vs + 64 * KS_STRIDE;    // 64*68

    const int tid = threadIdx.x;
    const int tx  = tid & 15;
    const int ty  = tid >> 4;
    const int bh  = blockIdx.y;         // b*16 + h
    const int qb  = blockIdx.x;         // query tile

    const float* Qg = g_Q + (size_t)bh * S_LEN * DKH;
    const float* Kg = g_K + (size_t)bh * S_LEN * DKH;
    const float* Vg = g_V + (size_t)bh * S_LEN * DKH;

    // Load Q tile (64x64)
    #pragma unroll
    for (int t = 0; t < 4; t++) {
        int idx = tid + t * 256;         // float4 index 0..1023
        int row = idx >> 4;
        int c4  = (idx & 15) << 2;
        *(float4*)&Qs[row * 64 + c4] =
            *(const float4*)&Qg[(qb * 64 + row) * DKH + c4];
    }

    float m_i[4], l_i[4], outv[4][4];
    #pragma unroll
    for (int i = 0; i < 4; i++) {
        m_i[i] = -1e30f;
        l_i[i] = 0.0f;
        #pragma unroll
        for (int j = 0; j < 4; j++) outv[i][j] = 0.0f;
    }

    for (int kt = 0; kt < S_LEN / 64; kt++) {
        __syncthreads();   // previous tile's Ps/Vs reads done
        #pragma unroll
        for (int t = 0; t < 4; t++) {
            int idx = tid + t * 256;
            int row = idx >> 4;
            int c4  = (idx & 15) << 2;
            *(float4*)&Ks[row * KS_STRIDE + c4] =
                *(const float4*)&Kg[(kt * 64 + row) * DKH + c4];
            *(float4*)&Vs[row * KS_STRIDE + c4] =
                *(const float4*)&Vg[(kt * 64 + row) * DKH + c4];
        }
        __syncthreads();

        // scores: s[i][j] = Q[ty*4+i,:] . K[j*16+tx,:]
        float s[4][4];
        #pragma unroll
        for (int i = 0; i < 4; i++)
            #pragma unroll
            for (int j = 0; j < 4; j++) s[i][j] = 0.0f;

        #pragma unroll 4
        for (int kk = 0; kk < 64; kk += 4) {
            float4 qv[4], kv[4];
            #pragma unroll
            for (int i = 0; i < 4; i++)
                qv[i] = *(const float4*)&Qs[(ty * 4 + i) * 64 + kk];
            #pragma unroll
            for (int j = 0; j < 4; j++)
                kv[j] = *(const float4*)&Ks[(j * 16 + tx) * KS_STRIDE + kk];
            #pragma unroll
            for (int i = 0; i < 4; i++)
                #pragma unroll
                for (int j = 0; j < 4; j++) {
                    s[i][j] = fmaf(qv[i].x, kv[j].x, s[i][j]);
                    s[i][j] = fmaf(qv[i].y, kv[j].y, s[i][j]);
                    s[i][j] = fmaf(qv[i].z, kv[j].z, s[i][j]);
                    s[i][j] = fmaf(qv[i].w, kv[j].w, s[i][j]);
                }
        }

        // online softmax update (row groups of 16 lanes share a q-row)
        #pragma unroll
        for (int i = 0; i < 4; i++) {
            #pragma unroll
            for (int j = 0; j < 4; j++) s[i][j] *= 0.125f;  // 1/sqrt(64)
            float tm = fmaxf(fmaxf(s[i][0], s[i][1]), fmaxf(s[i][2], s[i][3]));
            #pragma unroll
            for (int off = 8; off > 0; off >>= 1)
                tm = fmaxf(tm, __shfl_xor_sync(0xffffffffu, tm, off));
            float mn    = fmaxf(m_i[i], tm);
            float alpha = __expf(m_i[i] - mn);
            m_i[i] = mn;
            float rs = 0.0f;
            #pragma unroll
            for (int j = 0; j < 4; j++) {
                float p = __expf(s[i][j] - mn);
                s[i][j] = p;
                rs += p;
            }
            #pragma unroll
            for (int off = 8; off > 0; off >>= 1)
                rs += __shfl_xor_sync(0xffffffffu, rs, off);
            l_i[i] = l_i[i] * alpha + rs;
            #pragma unroll
            for (int j = 0; j < 4; j++) outv[i][j] *= alpha;
            #pragma unroll
            for (int j = 0; j < 4; j++)
                Ps[(ty * 4 + i) * KS_STRIDE + j * 16 + tx] = s[i][j];
        }
        __syncthreads();

        // out += P @ V  (out cols d = tx*4 + j)
        #pragma unroll 8
        for (int kk = 0; kk < 64; kk++) {
            float4 vv = *(const float4*)&Vs[kk * KS_STRIDE + tx * 4];
            #pragma unroll
            for (int i = 0; i < 4; i++) {
                float p = Ps[(ty * 4 + i) * KS_STRIDE + kk];
                outv[i][0] = fmaf(p, vv.x, outv[i][0]);
                outv[i][1] = fmaf(p, vv.y, outv[i][1]);
                outv[i][2] = fmaf(p, vv.z, outv[i][2]);
                outv[i][3] = fmaf(p, vv.w, outv[i][3]);
            }
        }
    }

    // epilogue: normalize and write O in [B,S,D] layout
    const int b = bh >> 4;
    const int h = bh & 15;
    #pragma unroll
    for (int i = 0; i < 4; i++) {
        int   sg  = qb * 64 + ty * 4 + i;
        float inv = 1.0f / l_i[i];
        float4 r;
        r.x = outv[i][0] * inv;
        r.y = outv[i][1] * inv;
        r.z = outv[i][2] * inv;
        r.w = outv[i][3] * inv;
        *(float4*)&O[((size_t)b * S_LEN + sg) * D_DIM + h * DKH + tx * 4] = r;
    }
}

// ---------------------------------------------------------------------------
extern "C" void kernel_launch(void* const* d_in, const int* in_sizes, int n_in,
                              void* d_out, int out_size)
{
    const float* x  = (const float*)d_in[0];
    const float* Wq = (const float*)d_in[1];
    const float* Wk = (const float*)d_in[2];
    const float* Wv = (const float*)d_in[3];
    const float* Wo = (const float*)d_in[4];
    float* out = (float*)d_out;

    cudaFuncSetAttribute(attn_kernel,
                         cudaFuncAttributeMaxDynamicSharedMemorySize, ATTN_SMEM);

    float* g_O_ptr = nullptr;
    cudaGetSymbolAddress((void**)&g_O_ptr, g_O);

    dim3 gqkv(M_TOT / 128, N_TOT / 128, 3);
    qkv_kernel<<<gqkv, 256>>>(x, Wq, Wk, Wv);

    dim3 gattn(S_LEN / 64, B_SZ * H_NUM);
    attn_kernel<<<gattn, 256, ATTN_SMEM>>>(g_O_ptr);

    dim3 gproj(M_TOT / 128, N_TOT / 128);
    proj_kernel<<<gproj, 256>>>(Wo, out);
}

// round 6
// speedup vs baseline: 1.3260x; 1.3260x over previous
#include <cuda_runtime.h>
#include <cuda_bf16.h>
#include <math.h>

// Problem constants
#define B_SZ   4
#define S_LEN  2048
#define D_DIM  1024
#define H_NUM  16
#define DKH    64
#define M_TOT  (B_SZ * S_LEN)     // 8192
#define K_TOT  D_DIM              // 1024
#define N_TOT  D_DIM              // 1024

// Scratch: Q,K,V in [B,H,S,DK] head-major layout; O in [B,S,D]
__device__ float g_Q[B_SZ * H_NUM * S_LEN * DKH];
__device__ float g_K[B_SZ * H_NUM * S_LEN * DKH];
__device__ float g_V[B_SZ * H_NUM * S_LEN * DKH];
__device__ float g_O[M_TOT * D_DIM];

// ===========================================================================
// Split-bf16 tensor-core GEMM: C[M,N] = A[M,K] @ W[N,K]^T   (fp32 in/out)
// Each fp32 value x = x_hi + x_lo (bf16 each). Expand K by 3 with slots:
//   A': [a_hi, a_hi, a_lo]   B': [b_hi, b_lo, b_hi]
// so sum over K' gives a_hi*b_hi + a_hi*b_lo + a_lo*b_hi  (error ~2^-16).
// Block 128x128, 256 thr (8 warps, 2x4, warp tile 64x32), per-stage KF=16
// fp32 -> 48 bf16. mma.sync.m16n8k16 + ldmatrix. Row stride 56 bf16 (112B)
// => conflict-free ldmatrix.
// ===========================================================================
#define KF       16          // fp32 k per stage
#define KB       48          // bf16 k per stage (3x)
#define LDSB     56          // bf16 row stride (padded)
#define NSTAGE   (K_TOT / KF)

__device__ __forceinline__ unsigned pack2(unsigned lo, unsigned hi) {
    return (lo & 0xFFFFu) | (hi << 16);
}

__device__ __forceinline__ void split1(float a, unsigned &h, unsigned &l) {
    unsigned ai = __float_as_uint(a);
    h = ai >> 16;                                    // truncated bf16 (exact)
    float hf = __uint_as_float(ai & 0xFFFF0000u);
    l = (unsigned)__bfloat16_as_ushort(__float2bfloat16(a - hf));
}

// 4 consecutive fp32 k -> 6 u32 (12 bf16), A-side slot order [h,h,l]
__device__ __forceinline__ void convA(float4 f, unsigned *u) {
    unsigned h0,l0,h1,l1,h2,l2,h3,l3;
    split1(f.x,h0,l0); split1(f.y,h1,l1); split1(f.z,h2,l2); split1(f.w,h3,l3);
    u[0]=pack2(h0,h0); u[1]=pack2(l0,h1); u[2]=pack2(h1,l1);
    u[3]=pack2(h2,h2); u[4]=pack2(l2,h3); u[5]=pack2(h3,l3);
}
// B-side slot order [h,l,h]
__device__ __forceinline__ void convB(float4 f, unsigned *u) {
    unsigned h0,l0,h1,l1,h2,l2,h3,l3;
    split1(f.x,h0,l0); split1(f.y,h1,l1); split1(f.z,h2,l2); split1(f.w,h3,l3);
    u[0]=pack2(h0,l0); u[1]=pack2(h0,h1); u[2]=pack2(l1,h1);
    u[3]=pack2(h2,l2); u[4]=pack2(h2,h3); u[5]=pack2(l3,h3);
}

__device__ __forceinline__ unsigned smem_u32(const void* p) {
    unsigned r;
    asm("{ .reg .u64 t; cvta.to.shared.u64 t, %1; cvt.u32.u64 %0, t; }"
        : "=r"(r) : "l"(p));
    return r;
}

__device__ __forceinline__ void ldsm_x4(unsigned addr, unsigned &r0, unsigned &r1,
                                        unsigned &r2, unsigned &r3) {
    asm volatile("ldmatrix.sync.aligned.m8n8.x4.shared.b16 {%0,%1,%2,%3}, [%4];"
                 : "=r"(r0), "=r"(r1), "=r"(r2), "=r"(r3) : "r"(addr));
}
__device__ __forceinline__ void ldsm_x2(unsigned addr, unsigned &r0, unsigned &r1) {
    asm volatile("ldmatrix.sync.aligned.m8n8.x2.shared.b16 {%0,%1}, [%2];"
                 : "=r"(r0), "=r"(r1) : "r"(addr));
}
__device__ __forceinline__ void mma16816(float &c0, float &c1, float &c2, float &c3,
                                         unsigned a0, unsigned a1, unsigned a2,
                                         unsigned a3, unsigned b0, unsigned b1) {
    asm volatile("mma.sync.aligned.m16n8k16.row.col.f32.bf16.bf16.f32 "
                 "{%0,%1,%2,%3}, {%4,%5,%6,%7}, {%8,%9}, {%0,%1,%2,%3};"
                 : "+f"(c0), "+f"(c1), "+f"(c2), "+f"(c3)
                 : "r"(a0), "r"(a1), "r"(a2), "r"(a3), "r"(b0), "r"(b1));
}

// Core: accumulates the full K into acc[4][4][4] (warp tile 64x32).
__device__ __forceinline__ void gemm_mma_core(const float* __restrict__ A,
                                              const float* __restrict__ W,
                                              float (&acc)[4][4][4],
                                              unsigned short* As,
                                              unsigned short* Bs)
{
    const int tid  = threadIdx.x;
    const int lane = tid & 31;
    const int wid  = tid >> 5;
    const int wm   = (wid & 1) * 64;
    const int wn   = (wid >> 1) * 32;
    const int lrow = tid >> 1;       // 0..127
    const int lhlf = tid & 1;        // 0/1: which 8 fp32 of the 16

    const unsigned asb = smem_u32(As);
    const unsigned bsb = smem_u32(Bs);

    const float* Ap = A + ((size_t)blockIdx.x * 128 + lrow) * K_TOT + lhlf * 8;
    const float* Wp = W + ((size_t)blockIdx.y * 128 + lrow) * K_TOT + lhlf * 8;

    float4 ra0 = *(const float4*)(Ap);
    float4 ra1 = *(const float4*)(Ap + 4);
    float4 rb0 = *(const float4*)(Wp);
    float4 rb1 = *(const float4*)(Wp + 4);

    const int soff = lrow * (LDSB * 2) + lhlf * 48;   // byte offset in smem

    #pragma unroll 1
    for (int s = 0; s < NSTAGE; s++) {
        // convert + store current stage
        unsigned ua[12], ub[12];
        convA(ra0, ua); convA(ra1, ua + 6);
        convB(rb0, ub); convB(rb1, ub + 6);
        *(uint4*)((char*)As + soff +  0) = make_uint4(ua[0], ua[1], ua[2],  ua[3]);
        *(uint4*)((char*)As + soff + 16) = make_uint4(ua[4], ua[5], ua[6],  ua[7]);
        *(uint4*)((char*)As + soff + 32) = make_uint4(ua[8], ua[9], ua[10], ua[11]);
        *(uint4*)((char*)Bs + soff +  0) = make_uint4(ub[0], ub[1], ub[2],  ub[3]);
        *(uint4*)((char*)Bs + soff + 16) = make_uint4(ub[4], ub[5], ub[6],  ub[7]);
        *(uint4*)((char*)Bs + soff + 32) = make_uint4(ub[8], ub[9], ub[10], ub[11]);
        __syncthreads();

        // prefetch next stage (overlaps mma below)
        if (s + 1 < NSTAGE) {
            Ap += KF; Wp += KF;
            ra0 = *(const float4*)(Ap);
            ra1 = *(const float4*)(Ap + 4);
            rb0 = *(const float4*)(Wp);
            rb1 = *(const float4*)(Wp + 4);
        }

        // 3 k16-steps over the 48 expanded bf16
        #pragma unroll
        for (int ks = 0; ks < 3; ks++) {
            unsigned a[4][4], b[4][2];
            #pragma unroll
            for (int i = 0; i < 4; i++) {
                unsigned addr = asb +
                    (((wm + 16 * i + (lane & 15)) * LDSB) +
                     (16 * ks + ((lane >> 4) << 3))) * 2;
                ldsm_x4(addr, a[i][0], a[i][1], a[i][2], a[i][3]);
            }
            #pragma unroll
            for (int j = 0; j < 4; j++) {
                unsigned addr = bsb +
                    (((wn + 8 * j + (lane & 7)) * LDSB) +
                     (16 * ks + (((lane >> 3) & 1) << 3))) * 2;
                ldsm_x2(addr, b[j][0], b[j][1]);
            }
            #pragma unroll
            for (int i = 0; i < 4; i++)
                #pragma unroll
                for (int j = 0; j < 4; j++)
                    mma16816(acc[i][j][0], acc[i][j][1], acc[i][j][2], acc[i][j][3],
                             a[i][0], a[i][1], a[i][2], a[i][3], b[j][0], b[j][1]);
        }
        __syncthreads();
    }
}

// QKV projection kernel: z selects weight + destination; scatter to [B,H,S,DK]
__global__ __launch_bounds__(256) void qkv_kernel(const float* __restrict__ x,
                                                  const float* __restrict__ Wq,
                                                  const float* __restrict__ Wk,
                                                  const float* __restrict__ Wv)
{
    __shared__ unsigned short As[128 * LDSB];
    __shared__ unsigned short Bs[128 * LDSB];
    const float* W = (blockIdx.z == 0) ? Wq : (blockIdx.z == 1) ? Wk : Wv;
    float* out     = (blockIdx.z == 0) ? g_Q : (blockIdx.z == 1) ? g_K : g_V;

    float acc[4][4][4];
    #pragma unroll
    for (int i = 0; i < 4; i++)
        #pragma unroll
        for (int j = 0; j < 4; j++)
            #pragma unroll
            for (int r = 0; r < 4; r++) acc[i][j][r] = 0.0f;

    gemm_mma_core(x, W, acc, As, Bs);

    const int lane = threadIdx.x & 31;
    const int wid  = threadIdx.x >> 5;
    const int wm   = (wid & 1) * 64;
    const int wn   = (wid >> 1) * 32;

    #pragma unroll
    for (int i = 0; i < 4; i++) {
        #pragma unroll
        for (int j = 0; j < 4; j++) {
            int n0 = blockIdx.y * 128 + wn + 8 * j + 2 * (lane & 3);
            int h  = n0 >> 6;
            int dk = n0 & 63;
            #pragma unroll
            for (int half = 0; half < 2; half++) {
                int m  = blockIdx.x * 128 + wm + 16 * i + (lane >> 2) + 8 * half;
                int b  = m >> 11;
                int sN = m & 2047;
                float2 v = make_float2(acc[i][j][2 * half], acc[i][j][2 * half + 1]);
                *(float2*)&out[((((size_t)(b << 4) + h) * S_LEN) + sN) * DKH + dk] = v;
            }
        }
    }
}

// Output projection kernel: d_out = g_O @ Wo^T
__global__ __launch_bounds__(256) void proj_kernel(const float* __restrict__ Wo,
                                                   float* __restrict__ C)
{
    __shared__ unsigned short As[128 * LDSB];
    __shared__ unsigned short Bs[128 * LDSB];

    float acc[4][4][4];
    #pragma unroll
    for (int i = 0; i < 4; i++)
        #pragma unroll
        for (int j = 0; j < 4; j++)
            #pragma unroll
            for (int r = 0; r < 4; r++) acc[i][j][r] = 0.0f;

    gemm_mma_core(g_O, Wo, acc, As, Bs);

    const int lane = threadIdx.x & 31;
    const int wid  = threadIdx.x >> 5;
    const int wm   = (wid & 1) * 64;
    const int wn   = (wid >> 1) * 32;

    #pragma unroll
    for (int i = 0; i < 4; i++) {
        #pragma unroll
        for (int j = 0; j < 4; j++) {
            int n0 = blockIdx.y * 128 + wn + 8 * j + 2 * (lane & 3);
            #pragma unroll
            for (int half = 0; half < 2; half++) {
                int m = blockIdx.x * 128 + wm + 16 * i + (lane >> 2) + 8 * half;
                float2 v = make_float2(acc[i][j][2 * half], acc[i][j][2 * half + 1]);
                *(float2*)&C[(size_t)m * N_TOT + n0] = v;
            }
        }
    }
}

// ---------------------------------------------------------------------------
// Flash attention: per (b,h), Q[2048,64] x K[2048,64]^T -> softmax -> x V
// (unchanged, fp32 FFMA — verified correct)
// ---------------------------------------------------------------------------
#define KS_STRIDE 68
#define ATTN_SMEM ((64 * 64 + 3 * 64 * KS_STRIDE) * 4)

__global__ __launch_bounds__(256) void attn_kernel(float* __restrict__ O)
{
    extern __shared__ float sm[];
    float* Qs = sm;                     // 64*64
    float* Ks = Qs + 64 * 64;           // 64*68
    float* Vs = Ks + 64 * KS_STRIDE;    // 64*68
    float* Ps = Vs + 64 * KS_STRIDE;    // 64*68

    const int tid = threadIdx.x;
    const int tx  = tid & 15;
    const int ty  = tid >> 4;
    const int bh  = blockIdx.y;         // b*16 + h
    const int qb  = blockIdx.x;         // query tile

    const float* Qg = g_Q + (size_t)bh * S_LEN * DKH;
    const float* Kg = g_K + (size_t)bh * S_LEN * DKH;
    const float* Vg = g_V + (size_t)bh * S_LEN * DKH;

    #pragma unroll
    for (int t = 0; t < 4; t++) {
        int idx = tid + t * 256;
        int row = idx >> 4;
        int c4  = (idx & 15) << 2;
        *(float4*)&Qs[row * 64 + c4] =
            *(const float4*)&Qg[(qb * 64 + row) * DKH + c4];
    }

    float m_i[4], l_i[4], outv[4][4];
    #pragma unroll
    for (int i = 0; i < 4; i++) {
        m_i[i] = -1e30f;
        l_i[i] = 0.0f;
        #pragma unroll
        for (int j = 0; j < 4; j++) outv[i][j] = 0.0f;
    }

    for (int kt = 0; kt < S_LEN / 64; kt++) {
        __syncthreads();
        #pragma unroll
        for (int t = 0; t < 4; t++) {
            int idx = tid + t * 256;
            int row = idx >> 4;
            int c4  = (idx & 15) << 2;
            *(float4*)&Ks[row * KS_STRIDE + c4] =
                *(const float4*)&Kg[(kt * 64 + row) * DKH + c4];
            *(float4*)&Vs[row * KS_STRIDE + c4] =
                *(const float4*)&Vg[(kt * 64 + row) * DKH + c4];
        }
        __syncthreads();

        float s[4][4];
        #pragma unroll
        for (int i = 0; i < 4; i++)
            #pragma unroll
            for (int j = 0; j < 4; j++) s[i][j] = 0.0f;

        #pragma unroll 4
        for (int kk = 0; kk < 64; kk += 4) {
            float4 qv[4], kv[4];
            #pragma unroll
            for (int i = 0; i < 4; i++)
                qv[i] = *(const float4*)&Qs[(ty * 4 + i) * 64 + kk];
            #pragma unroll
            for (int j = 0; j < 4; j++)
                kv[j] = *(const float4*)&Ks[(j * 16 + tx) * KS_STRIDE + kk];
            #pragma unroll
            for (int i = 0; i < 4; i++)
                #pragma unroll
                for (int j = 0; j < 4; j++) {
                    s[i][j] = fmaf(qv[i].x, kv[j].x, s[i][j]);
                    s[i][j] = fmaf(qv[i].y, kv[j].y, s[i][j]);
                    s[i][j] = fmaf(qv[i].z, kv[j].z, s[i][j]);
                    s[i][j] = fmaf(qv[i].w, kv[j].w, s[i][j]);
                }
        }

        #pragma unroll
        for (int i = 0; i < 4; i++) {
            #pragma unroll
            for (int j = 0; j < 4; j++) s[i][j] *= 0.125f;
            float tm = fmaxf(fmaxf(s[i][0], s[i][1]), fmaxf(s[i][2], s[i][3]));
            #pragma unroll
            for (int off = 8; off > 0; off >>= 1)
                tm = fmaxf(tm, __shfl_xor_sync(0xffffffffu, tm, off));
            float mn    = fmaxf(m_i[i], tm);
            float alpha = __expf(m_i[i] - mn);
            m_i[i] = mn;
            float rs = 0.0f;
            #pragma unroll
            for (int j = 0; j < 4; j++) {
                float p = __expf(s[i][j] - mn);
                s[i][j] = p;
                rs += p;
            }
            #pragma unroll
            for (int off = 8; off > 0; off >>= 1)
                rs += __shfl_xor_sync(0xffffffffu, rs, off);
            l_i[i] = l_i[i] * alpha + rs;
            #pragma unroll
            for (int j = 0; j < 4; j++) outv[i][j] *= alpha;
            #pragma unroll
            for (int j = 0; j < 4; j++)
                Ps[(ty * 4 + i) * KS_STRIDE + j * 16 + tx] = s[i][j];
        }
        __syncthreads();

        #pragma unroll 8
        for (int kk = 0; kk < 64; kk++) {
            float4 vv = *(const float4*)&Vs[kk * KS_STRIDE + tx * 4];
            #pragma unroll
            for (int i = 0; i < 4; i++) {
                float p = Ps[(ty * 4 + i) * KS_STRIDE + kk];
                outv[i][0] = fmaf(p, vv.x, outv[i][0]);
                outv[i][1] = fmaf(p, vv.y, outv[i][1]);
                outv[i][2] = fmaf(p, vv.z, outv[i][2]);
                outv[i][3] = fmaf(p, vv.w, outv[i][3]);
            }
        }
    }

    const int b = bh >> 4;
    const int h = bh & 15;
    #pragma unroll
    for (int i = 0; i < 4; i++) {
        int   sg  = qb * 64 + ty * 4 + i;
        float inv = 1.0f / l_i[i];
        float4 r;
        r.x = outv[i][0] * inv;
        r.y = outv[i][1] * inv;
        r.z = outv[i][2] * inv;
        r.w = outv[i][3] * inv;
        *(float4*)&O[((size_t)b * S_LEN + sg) * D_DIM + h * DKH + tx * 4] = r;
    }
}

// ---------------------------------------------------------------------------
extern "C" void kernel_launch(void* const* d_in, const int* in_sizes, int n_in,
                              void* d_out, int out_size)
{
    const float* x  = (const float*)d_in[0];
    const float* Wq = (const float*)d_in[1];
    const float* Wk = (const float*)d_in[2];
    const float* Wv = (const float*)d_in[3];
    const float* Wo = (const float*)d_in[4];
    float* out = (float*)d_out;

    cudaFuncSetAttribute(attn_kernel,
                         cudaFuncAttributeMaxDynamicSharedMemorySize, ATTN_SMEM);

    float* g_O_ptr = nullptr;
    cudaGetSymbolAddress((void**)&g_O_ptr, g_O);

    dim3 gqkv(M_TOT / 128, N_TOT / 128, 3);
    qkv_kernel<<<gqkv, 256>>>(x, Wq, Wk, Wv);

    dim3 gattn(S_LEN / 64, B_SZ * H_NUM);
    attn_kernel<<<gattn, 256, ATTN_SMEM>>>(g_O_ptr);

    dim3 gproj(M_TOT / 128, N_TOT / 128);
    proj_kernel<<<gproj, 256>>>(Wo, out);
}

// round 10
// speedup vs baseline: 1.7999x; 1.3574x over previous
#include <cuda_runtime.h>
#include <cuda_bf16.h>
#include <math.h>

// Problem constants
#define B_SZ   4
#define S_LEN  2048
#define D_DIM  1024
#define H_NUM  16
#define DKH    64
#define M_TOT  (B_SZ * S_LEN)     // 8192
#define K_TOT  D_DIM              // 1024
#define N_TOT  D_DIM              // 1024

// Scratch: Q,K,V packed split-bf16 (lo16=hi part, hi16=lo part) [B,H,S,DK]; O fp32 [B,S,D]
__device__ unsigned g_Qp[B_SZ * H_NUM * S_LEN * DKH];
__device__ unsigned g_Kp[B_SZ * H_NUM * S_LEN * DKH];
__device__ unsigned g_Vp[B_SZ * H_NUM * S_LEN * DKH];
__device__ float    g_O [M_TOT * D_DIM];

// ===========================================================================
// Split-bf16 helpers (x = x_hi + x_lo, both bf16; 3-term products)
// packed u32 layout: bits[0:16) = hi bf16, bits[16:32) = lo bf16
// ===========================================================================
__device__ __forceinline__ unsigned pack2(unsigned lo, unsigned hi) {
    return (lo & 0xFFFFu) | (hi << 16);
}
__device__ __forceinline__ void split1(float a, unsigned &h, unsigned &l) {
    unsigned ai = __float_as_uint(a);
    h = ai >> 16;                                    // truncated bf16
    float hf = __uint_as_float(ai & 0xFFFF0000u);
    l = (unsigned)__bfloat16_as_ushort(__float2bfloat16(a - hf));
}
// A slot order per element: [h, h, l]
__device__ __forceinline__ void convA(float4 f, unsigned *u) {
    unsigned h0,l0,h1,l1,h2,l2,h3,l3;
    split1(f.x,h0,l0); split1(f.y,h1,l1); split1(f.z,h2,l2); split1(f.w,h3,l3);
    u[0]=pack2(h0,h0); u[1]=pack2(l0,h1); u[2]=pack2(h1,l1);
    u[3]=pack2(h2,h2); u[4]=pack2(l2,h3); u[5]=pack2(h3,l3);
}
// B slot order per element: [h, l, h]
__device__ __forceinline__ void convB(float4 f, unsigned *u) {
    unsigned h0,l0,h1,l1,h2,l2,h3,l3;
    split1(f.x,h0,l0); split1(f.y,h1,l1); split1(f.z,h2,l2); split1(f.w,h3,l3);
    u[0]=pack2(h0,l0); u[1]=pack2(h0,h1); u[2]=pack2(l1,h1);
    u[3]=pack2(h2,l2); u[4]=pack2(h2,h3); u[5]=pack2(l3,h3);
}

__device__ __forceinline__ unsigned smem_u32(const void* p) {
    unsigned r;
    asm("{ .reg .u64 t; cvta.to.shared.u64 t, %1; cvt.u32.u64 %0, t; }"
        : "=r"(r) : "l"(p));
    return r;
}
__device__ __forceinline__ void ldsm_x4(unsigned addr, unsigned &r0, unsigned &r1,
                                        unsigned &r2, unsigned &r3) {
    asm volatile("ldmatrix.sync.aligned.m8n8.x4.shared.b16 {%0,%1,%2,%3}, [%4];"
                 : "=r"(r0), "=r"(r1), "=r"(r2), "=r"(r3) : "r"(addr));
}
__device__ __forceinline__ void ldsm_x2(unsigned addr, unsigned &r0, unsigned &r1) {
    asm volatile("ldmatrix.sync.aligned.m8n8.x2.shared.b16 {%0,%1}, [%2];"
                 : "=r"(r0), "=r"(r1) : "r"(addr));
}
__device__ __forceinline__ void ldsm_x2t(unsigned addr, unsigned &r0, unsigned &r1) {
    asm volatile("ldmatrix.sync.aligned.m8n8.x2.trans.shared.b16 {%0,%1}, [%2];"
                 : "=r"(r0), "=r"(r1) : "r"(addr));
}
__device__ __forceinline__ void mma16816(float &c0, float &c1, float &c2, float &c3,
                                         unsigned a0, unsigned a1, unsigned a2,
                                         unsigned a3, unsigned b0, unsigned b1) {
    asm volatile("mma.sync.aligned.m16n8k16.row.col.f32.bf16.bf16.f32 "
                 "{%0,%1,%2,%3}, {%4,%5,%6,%7}, {%8,%9}, {%0,%1,%2,%3};"
                 : "+f"(c0), "+f"(c1), "+f"(c2), "+f"(c3)
                 : "r"(a0), "r"(a1), "r"(a2), "r"(a3), "r"(b0), "r"(b1));
}

// ===========================================================================
// Projection GEMM (same proven core as before): C = A[M,K] @ W[N,K]^T
// ===========================================================================
#define KF       16
#define LDSB     56
#define NSTAGE   (K_TOT / KF)

__device__ __forceinline__ void gemm_mma_core(const float* __restrict__ A,
                                              const float* __restrict__ W,
                                              float (&acc)[4][4][4],
                                              unsigned short* As,
                                              unsigned short* Bs)
{
    const int tid  = threadIdx.x;
    const int lane = tid & 31;
    const int wid  = tid >> 5;
    const int wm   = (wid & 1) * 64;
    const int wn   = (wid >> 1) * 32;
    const int lrow = tid >> 1;
    const int lhlf = tid & 1;

    const unsigned asb = smem_u32(As);
    const unsigned bsb = smem_u32(Bs);

    const float* Ap = A + ((size_t)blockIdx.x * 128 + lrow) * K_TOT + lhlf * 8;
    const float* Wp = W + ((size_t)blockIdx.y * 128 + lrow) * K_TOT + lhlf * 8;

    float4 ra0 = *(const float4*)(Ap);
    float4 ra1 = *(const float4*)(Ap + 4);
    float4 rb0 = *(const float4*)(Wp);
    float4 rb1 = *(const float4*)(Wp + 4);

    const int soff = lrow * (LDSB * 2) + lhlf * 48;

    #pragma unroll 1
    for (int s = 0; s < NSTAGE; s++) {
        unsigned ua[12], ub[12];
        convA(ra0, ua); convA(ra1, ua + 6);
        convB(rb0, ub); convB(rb1, ub + 6);
        *(uint4*)((char*)As + soff +  0) = make_uint4(ua[0], ua[1], ua[2],  ua[3]);
        *(uint4*)((char*)As + soff + 16) = make_uint4(ua[4], ua[5], ua[6],  ua[7]);
        *(uint4*)((char*)As + soff + 32) = make_uint4(ua[8], ua[9], ua[10], ua[11]);
        *(uint4*)((char*)Bs + soff +  0) = make_uint4(ub[0], ub[1], ub[2],  ub[3]);
        *(uint4*)((char*)Bs + soff + 16) = make_uint4(ub[4], ub[5], ub[6],  ub[7]);
        *(uint4*)((char*)Bs + soff + 32) = make_uint4(ub[8], ub[9], ub[10], ub[11]);
        __syncthreads();

        if (s + 1 < NSTAGE) {
            Ap += KF; Wp += KF;
            ra0 = *(const float4*)(Ap);
            ra1 = *(const float4*)(Ap + 4);
            rb0 = *(const float4*)(Wp);
            rb1 = *(const float4*)(Wp + 4);
        }

        #pragma unroll
        for (int ks = 0; ks < 3; ks++) {
            unsigned a[4][4], b[4][2];
            #pragma unroll
            for (int i = 0; i < 4; i++) {
                unsigned addr = asb +
                    (((wm + 16 * i + (lane & 15)) * LDSB) +
                     (16 * ks + ((lane >> 4) << 3))) * 2;
                ldsm_x4(addr, a[i][0], a[i][1], a[i][2], a[i][3]);
            }
            #pragma unroll
            for (int j = 0; j < 4; j++) {
                unsigned addr = bsb +
                    (((wn + 8 * j + (lane & 7)) * LDSB) +
                     (16 * ks + (((lane >> 3) & 1) << 3))) * 2;
                ldsm_x2(addr, b[j][0], b[j][1]);
            }
            #pragma unroll
            for (int i = 0; i < 4; i++)
                #pragma unroll
                for (int j = 0; j < 4; j++)
                    mma16816(acc[i][j][0], acc[i][j][1], acc[i][j][2], acc[i][j][3],
                             a[i][0], a[i][1], a[i][2], a[i][3], b[j][0], b[j][1]);
        }
        __syncthreads();
    }
}

// QKV: writes packed split-bf16 u32 to g_Qp/g_Kp/g_Vp in [B,H,S,DK]
__global__ __launch_bounds__(256) void qkv_kernel(const float* __restrict__ x,
                                                  const float* __restrict__ Wq,
                                                  const float* __restrict__ Wk,
                                                  const float* __restrict__ Wv)
{
    __shared__ unsigned short As[128 * LDSB];
    __shared__ unsigned short Bs[128 * LDSB];
    const float* W = (blockIdx.z == 0) ? Wq : (blockIdx.z == 1) ? Wk : Wv;
    unsigned* out  = (blockIdx.z == 0) ? g_Qp : (blockIdx.z == 1) ? g_Kp : g_Vp;

    float acc[4][4][4];
    #pragma unroll
    for (int i = 0; i < 4; i++)
        #pragma unroll
        for (int j = 0; j < 4; j++)
            #pragma unroll
            for (int r = 0; r < 4; r++) acc[i][j][r] = 0.0f;

    gemm_mma_core(x, W, acc, As, Bs);

    const int lane = threadIdx.x & 31;
    const int wid  = threadIdx.x >> 5;
    const int wm   = (wid & 1) * 64;
    const int wn   = (wid >> 1) * 32;

    #pragma unroll
    for (int i = 0; i < 4; i++) {
        #pragma unroll
        for (int j = 0; j < 4; j++) {
            int n0 = blockIdx.y * 128 + wn + 8 * j + 2 * (lane & 3);
            int h  = n0 >> 6;
            int dk = n0 & 63;
            #pragma unroll
            for (int half = 0; half < 2; half++) {
                int m  = blockIdx.x * 128 + wm + 16 * i + (lane >> 2) + 8 * half;
                int b  = m >> 11;
                int sN = m & 2047;
                unsigned h0,l0,h1,l1;
                split1(acc[i][j][2*half],     h0, l0);
                split1(acc[i][j][2*half + 1], h1, l1);
                uint2 v = make_uint2(pack2(h0, l0), pack2(h1, l1));
                *(uint2*)&out[((((size_t)(b << 4) + h) * S_LEN) + sN) * DKH + dk] = v;
            }
        }
    }
}

// Output projection: d_out = g_O @ Wo^T (fp32 A, unchanged path)
__global__ __launch_bounds__(256) void proj_kernel(const float* __restrict__ Wo,
                                                   float* __restrict__ C)
{
    __shared__ unsigned short As[128 * LDSB];
    __shared__ unsigned short Bs[128 * LDSB];

    float acc[4][4][4];
    #pragma unroll
    for (int i = 0; i < 4; i++)
        #pragma unroll
        for (int j = 0; j < 4; j++)
            #pragma unroll
            for (int r = 0; r < 4; r++) acc[i][j][r] = 0.0f;

    gemm_mma_core(g_O, Wo, acc, As, Bs);

    const int lane = threadIdx.x & 31;
    const int wid  = threadIdx.x >> 5;
    const int wm   = (wid & 1) * 64;
    const int wn   = (wid >> 1) * 32;

    #pragma unroll
    for (int i = 0; i < 4; i++) {
        #pragma unroll
        for (int j = 0; j < 4; j++) {
            int n0 = blockIdx.y * 128 + wn + 8 * j + 2 * (lane & 3);
            #pragma unroll
            for (int half = 0; half < 2; half++) {
                int m = blockIdx.x * 128 + wm + 16 * i + (lane >> 2) + 8 * half;
                float2 v = make_float2(acc[i][j][2 * half], acc[i][j][2 * half + 1]);
                *(float2*)&C[(size_t)m * N_TOT + n0] = v;
            }
        }
    }
}

// ===========================================================================
// Tensor-core flash attention.
// Per CTA: one (b,h), 64 q-rows; 32 key tiles of 64. 256 thr, 8 warps (4x2):
// warp (wr=wid&3, wc=wid>>2) computes m16 (q) x n32 tile of S / O.
// Split-bf16 3-term for both QK^T (k-dim 64->192) and P@V (k-dim 64->192).
// ===========================================================================
#define ATT_QSTR 200                   // u16 row stride for Qe/Ke/Pe (192+8)
#define ATT_VSTR 72                    // u16 row stride for Ve (64+8)
#define OFF_QE   0
#define OFF_KE   25600
#define OFF_PE   51200
#define OFF_VE   76800                 // 192 rows x 72 u16
#define OFF_TMAX 104448
#define OFF_TSUM 104960
#define ATT_SMEM 105472

// expand one packed pair to A-slot pattern [h0,h0,l0,h1,h1,l1]
__device__ __forceinline__ void expA_pair(unsigned p0, unsigned p1, unsigned short* dst) {
    *(unsigned*)(dst)     = __byte_perm(p0, p0, 0x1010);
    *(unsigned*)(dst + 2) = __byte_perm(p0, p1, 0x5432);
    *(unsigned*)(dst + 4) = p1;
}
// B-slot pattern [h0,l0,h0,h1,l1,h1]
__device__ __forceinline__ void expB_pair(unsigned p0, unsigned p1, unsigned short* dst) {
    *(unsigned*)(dst)     = p0;
    *(unsigned*)(dst + 2) = __byte_perm(p0, p1, 0x5410);
    *(unsigned*)(dst + 4) = __byte_perm(p1, p1, 0x1032);
}

__global__ __launch_bounds__(256) void attn_mma_kernel(float* __restrict__ O)
{
    extern __shared__ char attsm[];
    unsigned short* Qe = (unsigned short*)(attsm + OFF_QE);
    unsigned short* Ke = (unsigned short*)(attsm + OFF_KE);
    unsigned short* Pe = (unsigned short*)(attsm + OFF_PE);
    unsigned short* Ve = (unsigned short*)(attsm + OFF_VE);
    float* tmax = (float*)(attsm + OFF_TMAX);
    float* tsum = (float*)(attsm + OFF_TSUM);
    const unsigned sbase = smem_u32(attsm);

    const int tid  = threadIdx.x;
    const int lane = tid & 31;
    const int wid  = tid >> 5;
    const int wr   = wid & 3;
    const int wc   = wid >> 2;
    const int bh   = blockIdx.y;
    const int qb   = blockIdx.x;
    const int r0   = wr * 16 + (lane >> 2);   // this thread's q-row (and r0+8)

    const unsigned* Qg = g_Qp + (size_t)bh * S_LEN * DKH + (size_t)qb * 64 * DKH;
    const unsigned* Kg = g_Kp + (size_t)bh * S_LEN * DKH;
    const unsigned* Vg = g_Vp + (size_t)bh * S_LEN * DKH;

    // ---- expand Q tile once: [64 q][192] A-pattern ----
    {
        int row = tid >> 2;
        int cb  = (tid & 3) * 16;
        const uint4* src = (const uint4*)(Qg + row * DKH + cb);
        uint4 w0 = src[0], w1 = src[1], w2 = src[2], w3 = src[3];
        unsigned short* dst = Qe + row * ATT_QSTR + 3 * cb;
        expA_pair(w0.x, w0.y, dst +  0); expA_pair(w0.z, w0.w, dst +  6);
        expA_pair(w1.x, w1.y, dst + 12); expA_pair(w1.z, w1.w, dst + 18);
        expA_pair(w2.x, w2.y, dst + 24); expA_pair(w2.z, w2.w, dst + 30);
        expA_pair(w3.x, w3.y, dst + 36); expA_pair(w3.z, w3.w, dst + 42);
    }

    float m0 = -1e30f, m1 = -1e30f, l0 = 0.0f, l1 = 0.0f;
    float oa[4][4];
    #pragma unroll
    for (int j = 0; j < 4; j++)
        #pragma unroll
        for (int r = 0; r < 4; r++) oa[j][r] = 0.0f;

    for (int kt = 0; kt < S_LEN / 64; kt++) {
        __syncthreads();   // previous tile's Ke/Ve/Pe reads complete (+Qe visible)

        // ---- expand K tile [64 key][192] B-pattern, V tile [192 k'][64 d] ----
        {
            int row = tid >> 2;
            int cb  = (tid & 3) * 16;
            const uint4* ksrc = (const uint4*)(Kg + (size_t)(kt * 64 + row) * DKH + cb);
            uint4 k0 = ksrc[0], k1 = ksrc[1], k2 = ksrc[2], k3 = ksrc[3];
            unsigned short* kd = Ke + row * ATT_QSTR + 3 * cb;
            expB_pair(k0.x, k0.y, kd +  0); expB_pair(k0.z, k0.w, kd +  6);
            expB_pair(k1.x, k1.y, kd + 12); expB_pair(k1.z, k1.w, kd + 18);
            expB_pair(k2.x, k2.y, kd + 24); expB_pair(k2.z, k2.w, kd + 30);
            expB_pair(k3.x, k3.y, kd + 36); expB_pair(k3.z, k3.w, kd + 42);

            const uint4* vsrc = (const uint4*)(Vg + (size_t)(kt * 64 + row) * DKH + cb);
            uint4 v0 = vsrc[0], v1 = vsrc[1], v2 = vsrc[2], v3 = vsrc[3];
            unsigned short* vd = Ve + (3 * row) * ATT_VSTR + cb;
            unsigned pp[8] = {v0.x, v0.y, v0.z, v0.w, v1.x, v1.y, v1.z, v1.w};
            unsigned qq[8] = {v2.x, v2.y, v2.z, v2.w, v3.x, v3.y, v3.z, v3.w};
            #pragma unroll
            for (int i = 0; i < 4; i++) {
                unsigned hh = __byte_perm(pp[2*i], pp[2*i+1], 0x5410);
                unsigned ll = __byte_perm(pp[2*i], pp[2*i+1], 0x7632);
                *(unsigned*)(vd + 2*i)                = hh;
                *(unsigned*)(vd + ATT_VSTR + 2*i)     = ll;
                *(unsigned*)(vd + 2*ATT_VSTR + 2*i)   = hh;
            }
            #pragma unroll
            for (int i = 0; i < 4; i++) {
                unsigned hh = __byte_perm(qq[2*i], qq[2*i+1], 0x5410);
                unsigned ll = __byte_perm(qq[2*i], qq[2*i+1], 0x7632);
                *(unsigned*)(vd + 8 + 2*i)              = hh;
                *(unsigned*)(vd + ATT_VSTR + 8 + 2*i)   = ll;
                *(unsigned*)(vd + 2*ATT_VSTR + 8 + 2*i) = hh;
            }
        }
        __syncthreads();

        // ---- S = Q K^T (expanded k = 192 -> 12 k16 steps) ----
        float sc[4][4];
        #pragma unroll
        for (int j = 0; j < 4; j++)
            #pragma unroll
            for (int r = 0; r < 4; r++) sc[j][r] = 0.0f;

        #pragma unroll
        for (int ks = 0; ks < 12; ks++) {
            unsigned a0,a1,a2,a3;
            unsigned aaddr = sbase + OFF_QE +
                (((wr * 16 + (lane & 15)) * ATT_QSTR) + 16 * ks + ((lane >> 4) << 3)) * 2;
            ldsm_x4(aaddr, a0, a1, a2, a3);
            unsigned b[4][2];
            #pragma unroll
            for (int j = 0; j < 4; j++) {
                unsigned baddr = sbase + OFF_KE +
                    (((wc * 32 + j * 8 + (lane & 7)) * ATT_QSTR) +
                     16 * ks + (((lane >> 3) & 1) << 3)) * 2;
                ldsm_x2(baddr, b[j][0], b[j][1]);
            }
            #pragma unroll
            for (int j = 0; j < 4; j++)
                mma16816(sc[j][0], sc[j][1], sc[j][2], sc[j][3],
                         a0, a1, a2, a3, b[j][0], b[j][1]);
        }

        // ---- online softmax ----
        #pragma unroll
        for (int j = 0; j < 4; j++)
            #pragma unroll
            for (int r = 0; r < 4; r++) sc[j][r] *= 0.125f;

        float mx0 = -1e30f, mx1 = -1e30f;
        #pragma unroll
        for (int j = 0; j < 4; j++) {
            mx0 = fmaxf(mx0, fmaxf(sc[j][0], sc[j][1]));
            mx1 = fmaxf(mx1, fmaxf(sc[j][2], sc[j][3]));
        }
        mx0 = fmaxf(mx0, __shfl_xor_sync(0xffffffffu, mx0, 1));
        mx0 = fmaxf(mx0, __shfl_xor_sync(0xffffffffu, mx0, 2));
        mx1 = fmaxf(mx1, __shfl_xor_sync(0xffffffffu, mx1, 1));
        mx1 = fmaxf(mx1, __shfl_xor_sync(0xffffffffu, mx1, 2));
        if ((lane & 3) == 0) {
            tmax[r0 * 2 + wc]       = mx0;
            tmax[(r0 + 8) * 2 + wc] = mx1;
        }
        __syncthreads();

        float mn0 = fmaxf(m0, fmaxf(tmax[r0 * 2], tmax[r0 * 2 + 1]));
        float mn1 = fmaxf(m1, fmaxf(tmax[(r0 + 8) * 2], tmax[(r0 + 8) * 2 + 1]));
        float al0 = __expf(m0 - mn0);
        float al1 = __expf(m1 - mn1);
        m0 = mn0; m1 = mn1;

        float s0 = 0.0f, s1 = 0.0f;
        #pragma unroll
        for (int j = 0; j < 4; j++) {
            sc[j][0] = __expf(sc[j][0] - mn0);
            sc[j][1] = __expf(sc[j][1] - mn0);
            sc[j][2] = __expf(sc[j][2] - mn1);
            sc[j][3] = __expf(sc[j][3] - mn1);
            s0 += sc[j][0] + sc[j][1];
            s1 += sc[j][2] + sc[j][3];
        }
        s0 += __shfl_xor_sync(0xffffffffu, s0, 1);
        s0 += __shfl_xor_sync(0xffffffffu, s0, 2);
        s1 += __shfl_xor_sync(0xffffffffu, s1, 1);
        s1 += __shfl_xor_sync(0xffffffffu, s1, 2);
        if ((lane & 3) == 0) {
            tsum[r0 * 2 + wc]       = s0;
            tsum[(r0 + 8) * 2 + wc] = s1;
        }

        // rescale O accumulators
        #pragma unroll
        for (int j = 0; j < 4; j++) {
            oa[j][0] *= al0; oa[j][1] *= al0;
            oa[j][2] *= al1; oa[j][3] *= al1;
        }

        // write expanded P (A-pattern) to smem
        #pragma unroll
        for (int j = 0; j < 4; j++) {
            int c0 = wc * 32 + j * 8 + (lane & 3) * 2;
            unsigned h0,lo0,h1,lo1;
            split1(sc[j][0], h0, lo0); split1(sc[j][1], h1, lo1);
            unsigned short* pd = Pe + r0 * ATT_QSTR + 3 * c0;
            *(unsigned*)(pd)     = pack2(h0, h0);
            *(unsigned*)(pd + 2) = pack2(lo0, h1);
            *(unsigned*)(pd + 4) = pack2(h1, lo1);
            split1(sc[j][2], h0, lo0); split1(sc[j][3], h1, lo1);
            pd = Pe + (r0 + 8) * ATT_QSTR + 3 * c0;
            *(unsigned*)(pd)     = pack2(h0, h0);
            *(unsigned*)(pd + 2) = pack2(lo0, h1);
            *(unsigned*)(pd + 4) = pack2(h1, lo1);
        }
        __syncthreads();

        l0 = l0 * al0 + tsum[r0 * 2] + tsum[r0 * 2 + 1];
        l1 = l1 * al1 + tsum[(r0 + 8) * 2] + tsum[(r0 + 8) * 2 + 1];

        // ---- O += P V (expanded k 192 -> 12 steps; V via ldmatrix trans) ----
        #pragma unroll
        for (int ks = 0; ks < 12; ks++) {
            unsigned a0,a1,a2,a3;
            unsigned aaddr = sbase + OFF_PE +
                (((wr * 16 + (lane & 15)) * ATT_QSTR) + 16 * ks + ((lane >> 4) << 3)) * 2;
            ldsm_x4(aaddr, a0, a1, a2, a3);
            unsigned b[4][2];
            #pragma unroll
            for (int j = 0; j < 4; j++) {
                unsigned baddr = sbase + OFF_VE +
                    (((16 * ks + (lane & 15)) * ATT_VSTR) + wc * 32 + j * 8) * 2;
                ldsm_x2t(baddr, b[j][0], b[j][1]);
            }
            #pragma unroll
            for (int j = 0; j < 4; j++)
                mma16816(oa[j][0], oa[j][1], oa[j][2], oa[j][3],
                         a0, a1, a2, a3, b[j][0], b[j][1]);
        }
    }

    // ---- epilogue ----
    const float inv0 = 1.0f / l0;
    const float inv1 = 1.0f / l1;
    const int b = bh >> 4;
    const int h = bh & 15;
    const int srow = qb * 64 + r0;
    #pragma unroll
    for (int j = 0; j < 4; j++) {
        int c0 = wc * 32 + j * 8 + (lane & 3) * 2;
        float2 v0 = make_float2(oa[j][0] * inv0, oa[j][1] * inv0);
        float2 v1 = make_float2(oa[j][2] * inv1, oa[j][3] * inv1);
        *(float2*)&O[((size_t)b * S_LEN + srow)     * D_DIM + h * DKH + c0] = v0;
        *(float2*)&O[((size_t)b * S_LEN + srow + 8) * D_DIM + h * DKH + c0] = v1;
    }
}

// ---------------------------------------------------------------------------
extern "C" void kernel_launch(void* const* d_in, const int* in_sizes, int n_in,
                              void* d_out, int out_size)
{
    const float* x  = (const float*)d_in[0];
    const float* Wq = (const float*)d_in[1];
    const float* Wk = (const float*)d_in[2];
    const float* Wv = (const float*)d_in[3];
    const float* Wo = (const float*)d_in[4];
    float* out = (float*)d_out;

    cudaFuncSetAttribute(attn_mma_kernel,
                         cudaFuncAttributeMaxDynamicSharedMemorySize, ATT_SMEM);

    float* g_O_ptr = nullptr;
    cudaGetSymbolAddress((void**)&g_O_ptr, g_O);

    dim3 gqkv(M_TOT / 128, N_TOT / 128, 3);
    qkv_kernel<<<gqkv, 256>>>(x, Wq, Wk, Wv);

    dim3 gattn(S_LEN / 64, B_SZ * H_NUM);
    attn_mma_kernel<<<gattn, 256, ATT_SMEM>>>(g_O_ptr);

    dim3 gproj(M_TOT / 128, N_TOT / 128);
    proj_kernel<<<gproj, 256>>>(Wo, out);
}

// round 16
// speedup vs baseline: 2.2744x; 1.2636x over previous
#include <cuda_runtime.h>
#include <cuda_bf16.h>
#include <math.h>

// Problem constants
#define B_SZ   4
#define S_LEN  2048
#define D_DIM  1024
#define H_NUM  16
#define DKH    64
#define M_TOT  (B_SZ * S_LEN)     // 8192
#define K_TOT  D_DIM              // 1024
#define N_TOT  D_DIM              // 1024

// Scratch: Q,K,V packed split-bf16 (lo16=hi, hi16=lo) [B,H,S,DK]; O fp32 [B,S,D]
__device__ unsigned g_Qp[B_SZ * H_NUM * S_LEN * DKH];
__device__ unsigned g_Kp[B_SZ * H_NUM * S_LEN * DKH];
__device__ unsigned g_Vp[B_SZ * H_NUM * S_LEN * DKH];
__device__ float    g_O [M_TOT * D_DIM];

// ===========================================================================
// Split-bf16 helpers
// ===========================================================================
__device__ __forceinline__ unsigned pack2(unsigned lo, unsigned hi) {
    return (lo & 0xFFFFu) | (hi << 16);
}
__device__ __forceinline__ void split1(float a, unsigned &h, unsigned &l) {
    unsigned ai = __float_as_uint(a);
    h = ai >> 16;
    float hf = __uint_as_float(ai & 0xFFFF0000u);
    l = (unsigned)__bfloat16_as_ushort(__float2bfloat16(a - hf));
}
// A slot order per element: [h, h, l]
__device__ __forceinline__ void convA(float4 f, unsigned *u) {
    unsigned h0,l0,h1,l1,h2,l2,h3,l3;
    split1(f.x,h0,l0); split1(f.y,h1,l1); split1(f.z,h2,l2); split1(f.w,h3,l3);
    u[0]=pack2(h0,h0); u[1]=pack2(l0,h1); u[2]=pack2(h1,l1);
    u[3]=pack2(h2,h2); u[4]=pack2(l2,h3); u[5]=pack2(h3,l3);
}
// B slot order per element: [h, l, h]
__device__ __forceinline__ void convB(float4 f, unsigned *u) {
    unsigned h0,l0,h1,l1,h2,l2,h3,l3;
    split1(f.x,h0,l0); split1(f.y,h1,l1); split1(f.z,h2,l2); split1(f.w,h3,l3);
    u[0]=pack2(h0,l0); u[1]=pack2(h0,h1); u[2]=pack2(l1,h1);
    u[3]=pack2(h2,l2); u[4]=pack2(h2,h3); u[5]=pack2(l3,h3);
}

__device__ __forceinline__ unsigned smem_u32(const void* p) {
    unsigned r;
    asm("{ .reg .u64 t; cvta.to.shared.u64 t, %1; cvt.u32.u64 %0, t; }"
        : "=r"(r) : "l"(p));
    return r;
}
__device__ __forceinline__ void ldsm_x4(unsigned addr, unsigned &r0, unsigned &r1,
                                        unsigned &r2, unsigned &r3) {
    asm volatile("ldmatrix.sync.aligned.m8n8.x4.shared.b16 {%0,%1,%2,%3}, [%4];"
                 : "=r"(r0), "=r"(r1), "=r"(r2), "=r"(r3) : "r"(addr));
}
__device__ __forceinline__ void ldsm_x2(unsigned addr, unsigned &r0, unsigned &r1) {
    asm volatile("ldmatrix.sync.aligned.m8n8.x2.shared.b16 {%0,%1}, [%2];"
                 : "=r"(r0), "=r"(r1) : "r"(addr));
}
__device__ __forceinline__ void ldsm_x2t(unsigned addr, unsigned &r0, unsigned &r1) {
    asm volatile("ldmatrix.sync.aligned.m8n8.x2.trans.shared.b16 {%0,%1}, [%2];"
                 : "=r"(r0), "=r"(r1) : "r"(addr));
}
__device__ __forceinline__ void mma16816(float &c0, float &c1, float &c2, float &c3,
                                         unsigned a0, unsigned a1, unsigned a2,
                                         unsigned a3, unsigned b0, unsigned b1) {
    asm volatile("mma.sync.aligned.m16n8k16.row.col.f32.bf16.bf16.f32 "
                 "{%0,%1,%2,%3}, {%4,%5,%6,%7}, {%8,%9}, {%0,%1,%2,%3};"
                 : "+f"(c0), "+f"(c1), "+f"(c2), "+f"(c3)
                 : "r"(a0), "r"(a1), "r"(a2), "r"(a3), "r"(b0), "r"(b1));
}

// ===========================================================================
// Projection GEMM (validated core, unchanged): C = A[M,K] @ W[N,K]^T
// ===========================================================================
#define KF       16
#define LDSB     56
#define NSTAGE   (K_TOT / KF)

__device__ __forceinline__ void gemm_mma_core(const float* __restrict__ A,
                                              const float* __restrict__ W,
                                              float (&acc)[4][4][4],
                                              unsigned short* As,
                                              unsigned short* Bs)
{
    const int tid  = threadIdx.x;
    const int lane = tid & 31;
    const int wid  = tid >> 5;
    const int wm   = (wid & 1) * 64;
    const int wn   = (wid >> 1) * 32;
    const int lrow = tid >> 1;
    const int lhlf = tid & 1;

    const unsigned asb = smem_u32(As);
    const unsigned bsb = smem_u32(Bs);

    const float* Ap = A + ((size_t)blockIdx.x * 128 + lrow) * K_TOT + lhlf * 8;
    const float* Wp = W + ((size_t)blockIdx.y * 128 + lrow) * K_TOT + lhlf * 8;

    float4 ra0 = *(const float4*)(Ap);
    float4 ra1 = *(const float4*)(Ap + 4);
    float4 rb0 = *(const float4*)(Wp);
    float4 rb1 = *(const float4*)(Wp + 4);

    const int soff = lrow * (LDSB * 2) + lhlf * 48;

    #pragma unroll 1
    for (int s = 0; s < NSTAGE; s++) {
        unsigned ua[12], ub[12];
        convA(ra0, ua); convA(ra1, ua + 6);
        convB(rb0, ub); convB(rb1, ub + 6);
        *(uint4*)((char*)As + soff +  0) = make_uint4(ua[0], ua[1], ua[2],  ua[3]);
        *(uint4*)((char*)As + soff + 16) = make_uint4(ua[4], ua[5], ua[6],  ua[7]);
        *(uint4*)((char*)As + soff + 32) = make_uint4(ua[8], ua[9], ua[10], ua[11]);
        *(uint4*)((char*)Bs + soff +  0) = make_uint4(ub[0], ub[1], ub[2],  ub[3]);
        *(uint4*)((char*)Bs + soff + 16) = make_uint4(ub[4], ub[5], ub[6],  ub[7]);
        *(uint4*)((char*)Bs + soff + 32) = make_uint4(ub[8], ub[9], ub[10], ub[11]);
        __syncthreads();

        if (s + 1 < NSTAGE) {
            Ap += KF; Wp += KF;
            ra0 = *(const float4*)(Ap);
            ra1 = *(const float4*)(Ap + 4);
            rb0 = *(const float4*)(Wp);
            rb1 = *(const float4*)(Wp + 4);
        }

        #pragma unroll
        for (int ks = 0; ks < 3; ks++) {
            unsigned a[4][4], b[4][2];
            #pragma unroll
            for (int i = 0; i < 4; i++) {
                unsigned addr = asb +
                    (((wm + 16 * i + (lane & 15)) * LDSB) +
                     (16 * ks + ((lane >> 4) << 3))) * 2;
                ldsm_x4(addr, a[i][0], a[i][1], a[i][2], a[i][3]);
            }
            #pragma unroll
            for (int j = 0; j < 4; j++) {
                unsigned addr = bsb +
                    (((wn + 8 * j + (lane & 7)) * LDSB) +
                     (16 * ks + (((lane >> 3) & 1) << 3))) * 2;
                ldsm_x2(addr, b[j][0], b[j][1]);
            }
            #pragma unroll
            for (int i = 0; i < 4; i++)
                #pragma unroll
                for (int j = 0; j < 4; j++)
                    mma16816(acc[i][j][0], acc[i][j][1], acc[i][j][2], acc[i][j][3],
                             a[i][0], a[i][1], a[i][2], a[i][3], b[j][0], b[j][1]);
        }
        __syncthreads();
    }
}

// QKV: writes packed split-bf16 u32 to g_Qp/g_Kp/g_Vp in [B,H,S,DK]
__global__ __launch_bounds__(256) void qkv_kernel(const float* __restrict__ x,
                                                  const float* __restrict__ Wq,
                                                  const float* __restrict__ Wk,
                                                  const float* __restrict__ Wv)
{
    __shared__ unsigned short As[128 * LDSB];
    __shared__ unsigned short Bs[128 * LDSB];
    const float* W = (blockIdx.z == 0) ? Wq : (blockIdx.z == 1) ? Wk : Wv;
    unsigned* out  = (blockIdx.z == 0) ? g_Qp : (blockIdx.z == 1) ? g_Kp : g_Vp;

    float acc[4][4][4];
    #pragma unroll
    for (int i = 0; i < 4; i++)
        #pragma unroll
        for (int j = 0; j < 4; j++)
            #pragma unroll
            for (int r = 0; r < 4; r++) acc[i][j][r] = 0.0f;

    gemm_mma_core(x, W, acc, As, Bs);

    const int lane = threadIdx.x & 31;
    const int wid  = threadIdx.x >> 5;
    const int wm   = (wid & 1) * 64;
    const int wn   = (wid >> 1) * 32;

    #pragma unroll
    for (int i = 0; i < 4; i++) {
        #pragma unroll
        for (int j = 0; j < 4; j++) {
            int n0 = blockIdx.y * 128 + wn + 8 * j + 2 * (lane & 3);
            int h  = n0 >> 6;
            int dk = n0 & 63;
            #pragma unroll
            for (int half = 0; half < 2; half++) {
                int m  = blockIdx.x * 128 + wm + 16 * i + (lane >> 2) + 8 * half;
                int b  = m >> 11;
                int sN = m & 2047;
                unsigned h0,l0,h1,l1;
                split1(acc[i][j][2*half],     h0, l0);
                split1(acc[i][j][2*half + 1], h1, l1);
                uint2 v = make_uint2(pack2(h0, l0), pack2(h1, l1));
                *(uint2*)&out[((((size_t)(b << 4) + h) * S_LEN) + sN) * DKH + dk] = v;
            }
        }
    }
}

// Output projection: d_out = g_O @ Wo^T
__global__ __launch_bounds__(256) void proj_kernel(const float* __restrict__ Wo,
                                                   float* __restrict__ C)
{
    __shared__ unsigned short As[128 * LDSB];
    __shared__ unsigned short Bs[128 * LDSB];

    float acc[4][4][4];
    #pragma unroll
    for (int i = 0; i < 4; i++)
        #pragma unroll
        for (int j = 0; j < 4; j++)
            #pragma unroll
            for (int r = 0; r < 4; r++) acc[i][j][r] = 0.0f;

    gemm_mma_core(g_O, Wo, acc, As, Bs);

    const int lane = threadIdx.x & 31;
    const int wid  = threadIdx.x >> 5;
    const int wm   = (wid & 1) * 64;
    const int wn   = (wid >> 1) * 32;

    #pragma unroll
    for (int i = 0; i < 4; i++) {
        #pragma unroll
        for (int j = 0; j < 4; j++) {
            int n0 = blockIdx.y * 128 + wn + 8 * j + 2 * (lane & 3);
            #pragma unroll
            for (int half = 0; half < 2; half++) {
                int m = blockIdx.x * 128 + wm + 16 * i + (lane >> 2) + 8 * half;
                float2 v = make_float2(acc[i][j][2 * half], acc[i][j][2 * half + 1]);
                *(float2*)&C[(size_t)m * N_TOT + n0] = v;
            }
        }
    }
}

// ===========================================================================
// Tensor-core flash attention v2: warps split M only, P stays in registers.
// Per CTA: one (b,h), 128 q-rows; 32 key tiles of 64. 8 warps x m16, n=64.
// Blocked split layout: X = [Xh(64) | Xl(64)] columns (K) / rows (V).
// Products: S = Qh*Kh + Ql*Kh + Qh*Kl ; O = Ph*Vh + Pl*Vh + Ph*Vl.
// ===========================================================================
#define AQ_STR 136        // u16 row stride Qe (128 cols + 8 pad)
#define AK_STR 136        // u16 row stride Ke
#define AV_STR 72         // u16 row stride Ve (64 cols + 8 pad)
#define OFF_QE 0
#define OFF_KE 34816      // 128 * 136 * 2
#define OFF_VE 52224      // + 64 * 136 * 2
#define ATT_SMEM 70656    // + 128 * 72 * 2

__global__ __launch_bounds__(256) void attn_mma_kernel(float* __restrict__ O)
{
    extern __shared__ char attsm[];
    unsigned short* Qe = (unsigned short*)(attsm + OFF_QE);
    unsigned short* Ke = (unsigned short*)(attsm + OFF_KE);
    unsigned short* Ve = (unsigned short*)(attsm + OFF_VE);
    const unsigned sbase = smem_u32(attsm);

    const int tid  = threadIdx.x;
    const int lane = tid & 31;
    const int wid  = tid >> 5;          // 0..7, warp q-rows wid*16..+15
    const int bh   = blockIdx.y;
    const int qb   = blockIdx.x;
    const int r0   = wid * 16 + (lane >> 2);

    const unsigned* Qg = g_Qp + (size_t)bh * S_LEN * DKH + (size_t)qb * 128 * DKH;
    const unsigned* Kg = g_Kp + (size_t)bh * S_LEN * DKH;
    const unsigned* Vg = g_Vp + (size_t)bh * S_LEN * DKH;

    // ---- expand Q once: 128 rows, blocked [Qh | Ql] ----
    {
        int row = tid >> 1;
        int cb  = (tid & 1) * 32;
        const uint4* src = (const uint4*)(Qg + row * DKH + cb);
        unsigned short* dh = Qe + row * AQ_STR + cb;
        unsigned short* dl = dh + 64;
        #pragma unroll
        for (int t = 0; t < 8; t++) {
            uint4 w = src[t];
            *(unsigned*)(dh + t * 4)     = __byte_perm(w.x, w.y, 0x5410);
            *(unsigned*)(dh + t * 4 + 2) = __byte_perm(w.z, w.w, 0x5410);
            *(unsigned*)(dl + t * 4)     = __byte_perm(w.x, w.y, 0x7632);
            *(unsigned*)(dl + t * 4 + 2) = __byte_perm(w.z, w.w, 0x7632);
        }
    }

    float m0 = -1e30f, m1 = -1e30f, l0 = 0.0f, l1 = 0.0f;
    float oa[8][4];
    #pragma unroll
    for (int j = 0; j < 8; j++)
        #pragma unroll
        for (int r = 0; r < 4; r++) oa[j][r] = 0.0f;

    for (int kt = 0; kt < S_LEN / 64; kt++) {
        __syncthreads();   // prior tile's Ke/Ve reads complete (also Qe visible)

        // ---- expand K tile [Kh|Kl] cols, V tile [Vh(rows 0-63)|Vl(64-127)] ----
        {
            int row = tid >> 2;
            int cb  = (tid & 3) * 16;
            const uint4* ksrc = (const uint4*)(Kg + (size_t)(kt * 64 + row) * DKH + cb);
            const uint4* vsrc = (const uint4*)(Vg + (size_t)(kt * 64 + row) * DKH + cb);
            unsigned short* kh = Ke + row * AK_STR + cb;
            unsigned short* kl = kh + 64;
            unsigned short* vh = Ve + row * AV_STR + cb;
            unsigned short* vl = Ve + (64 + row) * AV_STR + cb;
            #pragma unroll
            for (int t = 0; t < 4; t++) {
                uint4 w = ksrc[t];
                *(unsigned*)(kh + t * 4)     = __byte_perm(w.x, w.y, 0x5410);
                *(unsigned*)(kh + t * 4 + 2) = __byte_perm(w.z, w.w, 0x5410);
                *(unsigned*)(kl + t * 4)     = __byte_perm(w.x, w.y, 0x7632);
                *(unsigned*)(kl + t * 4 + 2) = __byte_perm(w.z, w.w, 0x7632);
                uint4 v = vsrc[t];
                *(unsigned*)(vh + t * 4)     = __byte_perm(v.x, v.y, 0x5410);
                *(unsigned*)(vh + t * 4 + 2) = __byte_perm(v.z, v.w, 0x5410);
                *(unsigned*)(vl + t * 4)     = __byte_perm(v.x, v.y, 0x7632);
                *(unsigned*)(vl + t * 4 + 2) = __byte_perm(v.z, v.w, 0x7632);
            }
        }
        __syncthreads();

        // ---- S = Qh*Kh + Ql*Kh + Qh*Kl  (per kk: cache Kh frags) ----
        float sc[8][4];
        #pragma unroll
        for (int j = 0; j < 8; j++)
            #pragma unroll
            for (int r = 0; r < 4; r++) sc[j][r] = 0.0f;

        #pragma unroll
        for (int kk = 0; kk < 4; kk++) {
            const unsigned arow = (wid * 16 + (lane & 15)) * AQ_STR;
            const unsigned koff = 16 * kk + ((lane >> 4) << 3);
            unsigned ah0, ah1, ah2, ah3;              // Qh frag
            ldsm_x4(sbase + OFF_QE + (arow + koff) * 2, ah0, ah1, ah2, ah3);

            unsigned kf[8][2];                        // Kh frags
            #pragma unroll
            for (int j = 0; j < 8; j++) {
                unsigned baddr = sbase + OFF_KE +
                    ((8 * j + (lane & 7)) * AK_STR + 16 * kk + (((lane >> 3) & 1) << 3)) * 2;
                ldsm_x2(baddr, kf[j][0], kf[j][1]);
            }
            #pragma unroll
            for (int j = 0; j < 8; j++)               // Qh * Kh
                mma16816(sc[j][0], sc[j][1], sc[j][2], sc[j][3],
                         ah0, ah1, ah2, ah3, kf[j][0], kf[j][1]);

            unsigned al0, al1, al2, al3;              // Ql frag
            ldsm_x4(sbase + OFF_QE + (arow + 64 + koff) * 2, al0, al1, al2, al3);
            #pragma unroll
            for (int j = 0; j < 8; j++)               // Ql * Kh
                mma16816(sc[j][0], sc[j][1], sc[j][2], sc[j][3],
                         al0, al1, al2, al3, kf[j][0], kf[j][1]);

            #pragma unroll
            for (int j = 0; j < 8; j++) {             // Qh * Kl
                unsigned baddr = sbase + OFF_KE +
                    ((8 * j + (lane & 7)) * AK_STR + 64 + 16 * kk + (((lane >> 3) & 1) << 3)) * 2;
                unsigned b0, b1;
                ldsm_x2(baddr, b0, b1);
                mma16816(sc[j][0], sc[j][1], sc[j][2], sc[j][3],
                         ah0, ah1, ah2, ah3, b0, b1);
            }
        }

        // ---- warp-local online softmax (rows fully owned by this warp) ----
        #pragma unroll
        for (int j = 0; j < 8; j++)
            #pragma unroll
            for (int r = 0; r < 4; r++) sc[j][r] *= 0.125f;   // 1/sqrt(64)

        float mx0 = -1e30f, mx1 = -1e30f;
        #pragma unroll
        for (int j = 0; j < 8; j++) {
            mx0 = fmaxf(mx0, fmaxf(sc[j][0], sc[j][1]));
            mx1 = fmaxf(mx1, fmaxf(sc[j][2], sc[j][3]));
        }
        mx0 = fmaxf(mx0, __shfl_xor_sync(0xffffffffu, mx0, 1));
        mx0 = fmaxf(mx0, __shfl_xor_sync(0xffffffffu, mx0, 2));
        mx1 = fmaxf(mx1, __shfl_xor_sync(0xffffffffu, mx1, 1));
        mx1 = fmaxf(mx1, __shfl_xor_sync(0xffffffffu, mx1, 2));

        float mn0 = fmaxf(m0, mx0);
        float mn1 = fmaxf(m1, mx1);
        float al0 = __expf(m0 - mn0);
        float al1 = __expf(m1 - mn1);
        m0 = mn0; m1 = mn1;

        float s0 = 0.0f, s1 = 0.0f;
        #pragma unroll
        for (int j = 0; j < 8; j++) {
            sc[j][0] = __expf(sc[j][0] - mn0);
            sc[j][1] = __expf(sc[j][1] - mn0);
            sc[j][2] = __expf(sc[j][2] - mn1);
            sc[j][3] = __expf(sc[j][3] - mn1);
            s0 += sc[j][0] + sc[j][1];
            s1 += sc[j][2] + sc[j][3];
        }
        s0 += __shfl_xor_sync(0xffffffffu, s0, 1);
        s0 += __shfl_xor_sync(0xffffffffu, s0, 2);
        s1 += __shfl_xor_sync(0xffffffffu, s1, 1);
        s1 += __shfl_xor_sync(0xffffffffu, s1, 2);
        l0 = l0 * al0 + s0;
        l1 = l1 * al1 + s1;

        #pragma unroll
        for (int j = 0; j < 8; j++) {
            oa[j][0] *= al0; oa[j][1] *= al0;
            oa[j][2] *= al1; oa[j][3] *= al1;
        }

        // ---- O += Ph*Vh + Pl*Vh + Ph*Vl (P in registers; cache Vh frags) ----
        #pragma unroll
        for (int kk = 0; kk < 4; kk++) {
            const int j0 = 2 * kk, j1 = 2 * kk + 1;
            // split P for keys 16kk..16kk+15 into bf16 hi/lo fragments
            unsigned h00,l00,h01,l01,h02,l02,h03,l03;
            unsigned h10,l10,h11,l11,h12,l12,h13,l13;
            split1(sc[j0][0], h00, l00); split1(sc[j0][1], h01, l01);
            split1(sc[j0][2], h02, l02); split1(sc[j0][3], h03, l03);
            split1(sc[j1][0], h10, l10); split1(sc[j1][1], h11, l11);
            split1(sc[j1][2], h12, l12); split1(sc[j1][3], h13, l13);
            unsigned pha0 = pack2(h00, h01), pha1 = pack2(h02, h03);
            unsigned pha2 = pack2(h10, h11), pha3 = pack2(h12, h13);
            unsigned pla0 = pack2(l00, l01), pla1 = pack2(l02, l03);
            unsigned pla2 = pack2(l10, l11), pla3 = pack2(l12, l13);

            unsigned vf[8][2];                        // Vh frags
            #pragma unroll
            for (int j = 0; j < 8; j++) {
                unsigned baddr = sbase + OFF_VE +
                    ((16 * kk + (lane & 15)) * AV_STR + 8 * j) * 2;
                ldsm_x2t(baddr, vf[j][0], vf[j][1]);
            }
            #pragma unroll
            for (int j = 0; j < 8; j++)               // Ph * Vh
                mma16816(oa[j][0], oa[j][1], oa[j][2], oa[j][3],
                         pha0, pha1, pha2, pha3, vf[j][0], vf[j][1]);
            #pragma unroll
            for (int j = 0; j < 8; j++)               // Pl * Vh
                mma16816(oa[j][0], oa[j][1], oa[j][2], oa[j][3],
                         pla0, pla1, pla2, pla3, vf[j][0], vf[j][1]);
            #pragma unroll
            for (int j = 0; j < 8; j++) {             // Ph * Vl
                unsigned baddr = sbase + OFF_VE +
                    ((64 + 16 * kk + (lane & 15)) * AV_STR + 8 * j) * 2;
                unsigned b0, b1;
                ldsm_x2t(baddr, b0, b1);
                mma16816(oa[j][0], oa[j][1], oa[j][2], oa[j][3],
                         pha0, pha1, pha2, pha3, b0, b1);
            }
        }
    }

    // ---- epilogue ----
    const float inv0 = 1.0f / l0;
    const float inv1 = 1.0f / l1;
    const int b = bh >> 4;
    const int h = bh & 15;
    const int srow = qb * 128 + r0;
    #pragma unroll
    for (int j = 0; j < 8; j++) {
        int c0 = 8 * j + (lane & 3) * 2;
        float2 v0 = make_float2(oa[j][0] * inv0, oa[j][1] * inv0);
        float2 v1 = make_float2(oa[j][2] * inv1, oa[j][3] * inv1);
        *(float2*)&O[((size_t)b * S_LEN + srow)     * D_DIM + h * DKH + c0] = v0;
        *(float2*)&O[((size_t)b * S_LEN + srow + 8) * D_DIM + h * DKH + c0] = v1;
    }
}

// ---------------------------------------------------------------------------
extern "C" void kernel_launch(void* const* d_in, const int* in_sizes, int n_in,
                              void* d_out, int out_size)
{
    const float* x  = (const float*)d_in[0];
    const float* Wq = (const float*)d_in[1];
    const float* Wk = (const float*)d_in[2];
    const float* Wv = (const float*)d_in[3];
    const float* Wo = (const float*)d_in[4];
    float* out = (float*)d_out;

    cudaFuncSetAttribute(attn_mma_kernel,
                         cudaFuncAttributeMaxDynamicSharedMemorySize, ATT_SMEM);

    float* g_O_ptr = nullptr;
    cudaGetSymbolAddress((void**)&g_O_ptr, g_O);

    dim3 gqkv(M_TOT / 128, N_TOT / 128, 3);
    qkv_kernel<<<gqkv, 256>>>(x, Wq, Wk, Wv);

    dim3 gattn(S_LEN / 128, B_SZ * H_NUM);
    attn_mma_kernel<<<gattn, 256, ATT_SMEM>>>(g_O_ptr);

    dim3 gproj(M_TOT / 128, N_TOT / 128);
    proj_kernel<<<gproj, 256>>>(Wo, out);
}

// round 17
// speedup vs baseline: 2.5091x; 1.1032x over previous
#include <cuda_runtime.h>
#include <cuda_bf16.h>
#include <math.h>

// Problem constants
#define B_SZ   4
#define S_LEN  2048
#define D_DIM  1024
#define H_NUM  16
#define DKH    64
#define M_TOT  (B_SZ * S_LEN)     // 8192
#define K_TOT  D_DIM              // 1024
#define N_TOT  D_DIM              // 1024

// Scratch: Q,K,V packed split-bf16 (lo16=hi, hi16=lo) [B,H,S,DK]; O fp32 [B,S,D]
__device__ unsigned g_Qp[B_SZ * H_NUM * S_LEN * DKH];
__device__ unsigned g_Kp[B_SZ * H_NUM * S_LEN * DKH];
__device__ unsigned g_Vp[B_SZ * H_NUM * S_LEN * DKH];
__device__ float    g_O [M_TOT * D_DIM];

// ===========================================================================
// Split-bf16 helpers
// ===========================================================================
__device__ __forceinline__ unsigned pack2(unsigned lo, unsigned hi) {
    return (lo & 0xFFFFu) | (hi << 16);
}
__device__ __forceinline__ void split1(float a, unsigned &h, unsigned &l) {
    unsigned ai = __float_as_uint(a);
    h = ai >> 16;
    float hf = __uint_as_float(ai & 0xFFFF0000u);
    l = (unsigned)__bfloat16_as_ushort(__float2bfloat16(a - hf));
}
// 4 fp32 -> 2 u32 of hi-bf16 pairs + 2 u32 of lo-bf16 pairs
__device__ __forceinline__ void convHL(float4 f, unsigned &h01, unsigned &h23,
                                       unsigned &l01, unsigned &l23) {
    unsigned h0,l0,h1,l1,h2,l2,h3,l3;
    split1(f.x,h0,l0); split1(f.y,h1,l1); split1(f.z,h2,l2); split1(f.w,h3,l3);
    h01 = pack2(h0,h1); h23 = pack2(h2,h3);
    l01 = pack2(l0,l1); l23 = pack2(l2,l3);
}

__device__ __forceinline__ unsigned smem_u32(const void* p) {
    unsigned r;
    asm("{ .reg .u64 t; cvta.to.shared.u64 t, %1; cvt.u32.u64 %0, t; }"
        : "=r"(r) : "l"(p));
    return r;
}
__device__ __forceinline__ void ldsm_x4(unsigned addr, unsigned &r0, unsigned &r1,
                                        unsigned &r2, unsigned &r3) {
    asm volatile("ldmatrix.sync.aligned.m8n8.x4.shared.b16 {%0,%1,%2,%3}, [%4];"
                 : "=r"(r0), "=r"(r1), "=r"(r2), "=r"(r3) : "r"(addr));
}
__device__ __forceinline__ void ldsm_x2(unsigned addr, unsigned &r0, unsigned &r1) {
    asm volatile("ldmatrix.sync.aligned.m8n8.x2.shared.b16 {%0,%1}, [%2];"
                 : "=r"(r0), "=r"(r1) : "r"(addr));
}
__device__ __forceinline__ void ldsm_x2t(unsigned addr, unsigned &r0, unsigned &r1) {
    asm volatile("ldmatrix.sync.aligned.m8n8.x2.trans.shared.b16 {%0,%1}, [%2];"
                 : "=r"(r0), "=r"(r1) : "r"(addr));
}
__device__ __forceinline__ void mma16816(float &c0, float &c1, float &c2, float &c3,
                                         unsigned a0, unsigned a1, unsigned a2,
                                         unsigned a3, unsigned b0, unsigned b1) {
    asm volatile("mma.sync.aligned.m16n8k16.row.col.f32.bf16.bf16.f32 "
                 "{%0,%1,%2,%3}, {%4,%5,%6,%7}, {%8,%9}, {%0,%1,%2,%3};"
                 : "+f"(c0), "+f"(c1), "+f"(c2), "+f"(c3)
                 : "r"(a0), "r"(a1), "r"(a2), "r"(a3), "r"(b0), "r"(b1));
}

// ===========================================================================
// Projection GEMM, blocked-split edition: C = A[M,K] @ W[N,K]^T
// Per stage KF=16 fp32 -> row layout [h(16) | l(16)] bf16, stride 40 u16.
// Passes: Ah*Bh + Al*Bh + Ah*Bl (Ah and Bh fragments reused).
// ===========================================================================
#define KF       16
#define LDSB2    40
#define NSTAGE   (K_TOT / KF)

__device__ __forceinline__ void gemm_mma_core(const float* __restrict__ A,
                                              const float* __restrict__ W,
                                              float (&acc)[4][4][4],
                                              unsigned short* As,
                                              unsigned short* Bs)
{
    const int tid  = threadIdx.x;
    const int lane = tid & 31;
    const int wid  = tid >> 5;
    const int wm   = (wid & 1) * 64;
    const int wn   = (wid >> 1) * 32;
    const int lrow = tid >> 1;
    const int lhlf = tid & 1;

    const unsigned asb = smem_u32(As);
    const unsigned bsb = smem_u32(Bs);

    const float* Ap = A + ((size_t)blockIdx.x * 128 + lrow) * K_TOT + lhlf * 8;
    const float* Wp = W + ((size_t)blockIdx.y * 128 + lrow) * K_TOT + lhlf * 8;

    float4 ra0 = *(const float4*)(Ap);
    float4 ra1 = *(const float4*)(Ap + 4);
    float4 rb0 = *(const float4*)(Wp);
    float4 rb1 = *(const float4*)(Wp + 4);

    const int soff = (lrow * LDSB2 + lhlf * 8) * 2;   // byte offset, h block

    #pragma unroll 1
    for (int s = 0; s < NSTAGE; s++) {
        unsigned a0h01,a0h23,a0l01,a0l23, a1h01,a1h23,a1l01,a1l23;
        unsigned b0h01,b0h23,b0l01,b0l23, b1h01,b1h23,b1l01,b1l23;
        convHL(ra0, a0h01, a0h23, a0l01, a0l23);
        convHL(ra1, a1h01, a1h23, a1l01, a1l23);
        convHL(rb0, b0h01, b0h23, b0l01, b0l23);
        convHL(rb1, b1h01, b1h23, b1l01, b1l23);
        *(uint4*)((char*)As + soff)      = make_uint4(a0h01, a0h23, a1h01, a1h23);
        *(uint4*)((char*)As + soff + 32) = make_uint4(a0l01, a0l23, a1l01, a1l23);
        *(uint4*)((char*)Bs + soff)      = make_uint4(b0h01, b0h23, b1h01, b1h23);
        *(uint4*)((char*)Bs + soff + 32) = make_uint4(b0l01, b0l23, b1l01, b1l23);
        __syncthreads();

        if (s + 1 < NSTAGE) {
            Ap += KF; Wp += KF;
            ra0 = *(const float4*)(Ap);
            ra1 = *(const float4*)(Ap + 4);
            rb0 = *(const float4*)(Wp);
            rb1 = *(const float4*)(Wp + 4);
        }

        const unsigned koff = (lane >> 4) << 3;            // A frag col sel
        const unsigned bkoff = ((lane >> 3) & 1) << 3;     // B frag col sel

        unsigned ah[4][4], bh[4][2];
        #pragma unroll
        for (int i = 0; i < 4; i++) {
            unsigned addr = asb +
                (((wm + 16 * i + (lane & 15)) * LDSB2) + koff) * 2;
            ldsm_x4(addr, ah[i][0], ah[i][1], ah[i][2], ah[i][3]);
        }
        #pragma unroll
        for (int j = 0; j < 4; j++) {
            unsigned addr = bsb +
                (((wn + 8 * j + (lane & 7)) * LDSB2) + bkoff) * 2;
            ldsm_x2(addr, bh[j][0], bh[j][1]);
        }
        #pragma unroll
        for (int i = 0; i < 4; i++)                      // Ah * Bh
            #pragma unroll
            for (int j = 0; j < 4; j++)
                mma16816(acc[i][j][0], acc[i][j][1], acc[i][j][2], acc[i][j][3],
                         ah[i][0], ah[i][1], ah[i][2], ah[i][3], bh[j][0], bh[j][1]);

        #pragma unroll
        for (int i = 0; i < 4; i++) {                    // Al * Bh
            unsigned al0, al1, al2, al3;
            unsigned addr = asb +
                (((wm + 16 * i + (lane & 15)) * LDSB2) + 16 + koff) * 2;
            ldsm_x4(addr, al0, al1, al2, al3);
            #pragma unroll
            for (int j = 0; j < 4; j++)
                mma16816(acc[i][j][0], acc[i][j][1], acc[i][j][2], acc[i][j][3],
                         al0, al1, al2, al3, bh[j][0], bh[j][1]);
        }

        #pragma unroll
        for (int j = 0; j < 4; j++) {                    // Ah * Bl
            unsigned bl0, bl1;
            unsigned addr = bsb +
                (((wn + 8 * j + (lane & 7)) * LDSB2) + 16 + bkoff) * 2;
            ldsm_x2(addr, bl0, bl1);
            #pragma unroll
            for (int i = 0; i < 4; i++)
                mma16816(acc[i][j][0], acc[i][j][1], acc[i][j][2], acc[i][j][3],
                         ah[i][0], ah[i][1], ah[i][2], ah[i][3], bl0, bl1);
        }
        __syncthreads();
    }
}

// QKV: writes packed split-bf16 u32 to g_Qp/g_Kp/g_Vp in [B,H,S,DK]
__global__ __launch_bounds__(256) void qkv_kernel(const float* __restrict__ x,
                                                  const float* __restrict__ Wq,
                                                  const float* __restrict__ Wk,
                                                  const float* __restrict__ Wv)
{
    __shared__ unsigned short As[128 * LDSB2];
    __shared__ unsigned short Bs[128 * LDSB2];
    const float* W = (blockIdx.z == 0) ? Wq : (blockIdx.z == 1) ? Wk : Wv;
    unsigned* out  = (blockIdx.z == 0) ? g_Qp : (blockIdx.z == 1) ? g_Kp : g_Vp;

    float acc[4][4][4];
    #pragma unroll
    for (int i = 0; i < 4; i++)
        #pragma unroll
        for (int j = 0; j < 4; j++)
            #pragma unroll
            for (int r = 0; r < 4; r++) acc[i][j][r] = 0.0f;

    gemm_mma_core(x, W, acc, As, Bs);

    const int lane = threadIdx.x & 31;
    const int wid  = threadIdx.x >> 5;
    const int wm   = (wid & 1) * 64;
    const int wn   = (wid >> 1) * 32;

    #pragma unroll
    for (int i = 0; i < 4; i++) {
        #pragma unroll
        for (int j = 0; j < 4; j++) {
            int n0 = blockIdx.y * 128 + wn + 8 * j + 2 * (lane & 3);
            int h  = n0 >> 6;
            int dk = n0 & 63;
            #pragma unroll
            for (int half = 0; half < 2; half++) {
                int m  = blockIdx.x * 128 + wm + 16 * i + (lane >> 2) + 8 * half;
                int b  = m >> 11;
                int sN = m & 2047;
                unsigned h0,l0,h1,l1;
                split1(acc[i][j][2*half],     h0, l0);
                split1(acc[i][j][2*half + 1], h1, l1);
                uint2 v = make_uint2(pack2(h0, l0), pack2(h1, l1));
                *(uint2*)&out[((((size_t)(b << 4) + h) * S_LEN) + sN) * DKH + dk] = v;
            }
        }
    }
}

// Output projection: d_out = g_O @ Wo^T
__global__ __launch_bounds__(256) void proj_kernel(const float* __restrict__ Wo,
                                                   float* __restrict__ C)
{
    __shared__ unsigned short As[128 * LDSB2];
    __shared__ unsigned short Bs[128 * LDSB2];

    float acc[4][4][4];
    #pragma unroll
    for (int i = 0; i < 4; i++)
        #pragma unroll
        for (int j = 0; j < 4; j++)
            #pragma unroll
            for (int r = 0; r < 4; r++) acc[i][j][r] = 0.0f;

    gemm_mma_core(g_O, Wo, acc, As, Bs);

    const int lane = threadIdx.x & 31;
    const int wid  = threadIdx.x >> 5;
    const int wm   = (wid & 1) * 64;
    const int wn   = (wid >> 1) * 32;

    #pragma unroll
    for (int i = 0; i < 4; i++) {
        #pragma unroll
        for (int j = 0; j < 4; j++) {
            int n0 = blockIdx.y * 128 + wn + 8 * j + 2 * (lane & 3);
            #pragma unroll
            for (int half = 0; half < 2; half++) {
                int m = blockIdx.x * 128 + wm + 16 * i + (lane >> 2) + 8 * half;
                float2 v = make_float2(acc[i][j][2 * half], acc[i][j][2 * half + 1]);
                *(float2*)&C[(size_t)m * N_TOT + n0] = v;
            }
        }
    }
}

// ===========================================================================
// Tensor-core flash attention v2 (measured, unchanged): warps split M only,
// P stays in registers, blocked [Xh|Xl] split, warp-local softmax.
// ===========================================================================
#define AQ_STR 136        // u16 row stride Qe (128 cols + 8 pad)
#define AK_STR 136        // u16 row stride Ke
#define AV_STR 72         // u16 row stride Ve (64 cols + 8 pad)
#define OFF_QE 0
#define OFF_KE 34816      // 128 * 136 * 2
#define OFF_VE 52224      // + 64 * 136 * 2
#define ATT_SMEM 70656    // + 128 * 72 * 2

__global__ __launch_bounds__(256) void attn_mma_kernel(float* __restrict__ O)
{
    extern __shared__ char attsm[];
    unsigned short* Qe = (unsigned short*)(attsm + OFF_QE);
    unsigned short* Ke = (unsigned short*)(attsm + OFF_KE);
    unsigned short* Ve = (unsigned short*)(attsm + OFF_VE);
    const unsigned sbase = smem_u32(attsm);

    const int tid  = threadIdx.x;
    const int lane = tid & 31;
    const int wid  = tid >> 5;          // 0..7, warp q-rows wid*16..+15
    const int bh   = blockIdx.y;
    const int qb   = blockIdx.x;
    const int r0   = wid * 16 + (lane >> 2);

    const unsigned* Qg = g_Qp + (size_t)bh * S_LEN * DKH + (size_t)qb * 128 * DKH;
    const unsigned* Kg = g_Kp + (size_t)bh * S_LEN * DKH;
    const unsigned* Vg = g_Vp + (size_t)bh * S_LEN * DKH;

    // ---- expand Q once: 128 rows, blocked [Qh | Ql] ----
    {
        int row = tid >> 1;
        int cb  = (tid & 1) * 32;
        const uint4* src = (const uint4*)(Qg + row * DKH + cb);
        unsigned short* dh = Qe + row * AQ_STR + cb;
        unsigned short* dl = dh + 64;
        #pragma unroll
        for (int t = 0; t < 8; t++) {
            uint4 w = src[t];
            *(unsigned*)(dh + t * 4)     = __byte_perm(w.x, w.y, 0x5410);
            *(unsigned*)(dh + t * 4 + 2) = __byte_perm(w.z, w.w, 0x5410);
            *(unsigned*)(dl + t * 4)     = __byte_perm(w.x, w.y, 0x7632);
            *(unsigned*)(dl + t * 4 + 2) = __byte_perm(w.z, w.w, 0x7632);
        }
    }

    float m0 = -1e30f, m1 = -1e30f, l0 = 0.0f, l1 = 0.0f;
    float oa[8][4];
    #pragma unroll
    for (int j = 0; j < 8; j++)
        #pragma unroll
        for (int r = 0; r < 4; r++) oa[j][r] = 0.0f;

    for (int kt = 0; kt < S_LEN / 64; kt++) {
        __syncthreads();   // prior tile's Ke/Ve reads complete (also Qe visible)

        // ---- expand K tile [Kh|Kl] cols, V tile [Vh(rows 0-63)|Vl(64-127)] ----
        {
            int row = tid >> 2;
            int cb  = (tid & 3) * 16;
            const uint4* ksrc = (const uint4*)(Kg + (size_t)(kt * 64 + row) * DKH + cb);
            const uint4* vsrc = (const uint4*)(Vg + (size_t)(kt * 64 + row) * DKH + cb);
            unsigned short* kh = Ke + row * AK_STR + cb;
            unsigned short* kl = kh + 64;
            unsigned short* vh = Ve + row * AV_STR + cb;
            unsigned short* vl = Ve + (64 + row) * AV_STR + cb;
            #pragma unroll
            for (int t = 0; t < 4; t++) {
                uint4 w = ksrc[t];
                *(unsigned*)(kh + t * 4)     = __byte_perm(w.x, w.y, 0x5410);
                *(unsigned*)(kh + t * 4 + 2) = __byte_perm(w.z, w.w, 0x5410);
                *(unsigned*)(kl + t * 4)     = __byte_perm(w.x, w.y, 0x7632);
                *(unsigned*)(kl + t * 4 + 2) = __byte_perm(w.z, w.w, 0x7632);
                uint4 v = vsrc[t];
                *(unsigned*)(vh + t * 4)     = __byte_perm(v.x, v.y, 0x5410);
                *(unsigned*)(vh + t * 4 + 2) = __byte_perm(v.z, v.w, 0x5410);
                *(unsigned*)(vl + t * 4)     = __byte_perm(v.x, v.y, 0x7632);
                *(unsigned*)(vl + t * 4 + 2) = __byte_perm(v.z, v.w, 0x7632);
            }
        }
        __syncthreads();

        // ---- S = Qh*Kh + Ql*Kh + Qh*Kl  (per kk: cache Kh frags) ----
        float sc[8][4];
        #pragma unroll
        for (int j = 0; j < 8; j++)
            #pragma unroll
            for (int r = 0; r < 4; r++) sc[j][r] = 0.0f;

        #pragma unroll
        for (int kk = 0; kk < 4; kk++) {
            const unsigned arow = (wid * 16 + (lane & 15)) * AQ_STR;
            const unsigned koff = 16 * kk + ((lane >> 4) << 3);
            unsigned ah0, ah1, ah2, ah3;              // Qh frag
            ldsm_x4(sbase + OFF_QE + (arow + koff) * 2, ah0, ah1, ah2, ah3);

            unsigned kf[8][2];                        // Kh frags
            #pragma unroll
            for (int j = 0; j < 8; j++) {
                unsigned baddr = sbase + OFF_KE +
                    ((8 * j + (lane & 7)) * AK_STR + 16 * kk + (((lane >> 3) & 1) << 3)) * 2;
                ldsm_x2(baddr, kf[j][0], kf[j][1]);
            }
            #pragma unroll
            for (int j = 0; j < 8; j++)               // Qh * Kh
                mma16816(sc[j][0], sc[j][1], sc[j][2], sc[j][3],
                         ah0, ah1, ah2, ah3, kf[j][0], kf[j][1]);

            unsigned al0, al1, al2, al3;              // Ql frag
            ldsm_x4(sbase + OFF_QE + (arow + 64 + koff) * 2, al0, al1, al2, al3);
            #pragma unroll
            for (int j = 0; j < 8; j++)               // Ql * Kh
                mma16816(sc[j][0], sc[j][1], sc[j][2], sc[j][3],
                         al0, al1, al2, al3, kf[j][0], kf[j][1]);

            #pragma unroll
            for (int j = 0; j < 8; j++) {             // Qh * Kl
                unsigned baddr = sbase + OFF_KE +
                    ((8 * j + (lane & 7)) * AK_STR + 64 + 16 * kk + (((lane >> 3) & 1) << 3)) * 2;
                unsigned b0, b1;
                ldsm_x2(baddr, b0, b1);
                mma16816(sc[j][0], sc[j][1], sc[j][2], sc[j][3],
                         ah0, ah1, ah2, ah3, b0, b1);
            }
        }

        // ---- warp-local online softmax (rows fully owned by this warp) ----
        #pragma unroll
        for (int j = 0; j < 8; j++)
            #pragma unroll
            for (int r = 0; r < 4; r++) sc[j][r] *= 0.125f;   // 1/sqrt(64)

        float mx0 = -1e30f, mx1 = -1e30f;
        #pragma unroll
        for (int j = 0; j < 8; j++) {
            mx0 = fmaxf(mx0, fmaxf(sc[j][0], sc[j][1]));
            mx1 = fmaxf(mx1, fmaxf(sc[j][2], sc[j][3]));
        }
        mx0 = fmaxf(mx0, __shfl_xor_sync(0xffffffffu, mx0, 1));
        mx0 = fmaxf(mx0, __shfl_xor_sync(0xffffffffu, mx0, 2));
        mx1 = fmaxf(mx1, __shfl_xor_sync(0xffffffffu, mx1, 1));
        mx1 = fmaxf(mx1, __shfl_xor_sync(0xffffffffu, mx1, 2));

        float mn0 = fmaxf(m0, mx0);
        float mn1 = fmaxf(m1, mx1);
        float al0 = __expf(m0 - mn0);
        float al1 = __expf(m1 - mn1);
        m0 = mn0; m1 = mn1;

        float s0 = 0.0f, s1 = 0.0f;
        #pragma unroll
        for (int j = 0; j < 8; j++) {
            sc[j][0] = __expf(sc[j][0] - mn0);
            sc[j][1] = __expf(sc[j][1] - mn0);
            sc[j][2] = __expf(sc[j][2] - mn1);
            sc[j][3] = __expf(sc[j][3] - mn1);
            s0 += sc[j][0] + sc[j][1];
            s1 += sc[j][2] + sc[j][3];
        }
        s0 += __shfl_xor_sync(0xffffffffu, s0, 1);
        s0 += __shfl_xor_sync(0xffffffffu, s0, 2);
        s1 += __shfl_xor_sync(0xffffffffu, s1, 1);
        s1 += __shfl_xor_sync(0xffffffffu, s1, 2);
        l0 = l0 * al0 + s0;
        l1 = l1 * al1 + s1;

        #pragma unroll
        for (int j = 0; j < 8; j++) {
            oa[j][0] *= al0; oa[j][1] *= al0;
            oa[j][2] *= al1; oa[j][3] *= al1;
        }

        // ---- O += Ph*Vh + Pl*Vh + Ph*Vl (P in registers; cache Vh frags) ----
        #pragma unroll
        for (int kk = 0; kk < 4; kk++) {
            const int j0 = 2 * kk, j1 = 2 * kk + 1;
            unsigned h00,l00,h01,l01,h02,l02,h03,l03;
            unsigned h10,l10,h11,l11,h12,l12,h13,l13;
            split1(sc[j0][0], h00, l00); split1(sc[j0][1], h01, l01);
            split1(sc[j0][2], h02, l02); split1(sc[j0][3], h03, l03);
            split1(sc[j1][0], h10, l10); split1(sc[j1][1], h11, l11);
            split1(sc[j1][2], h12, l12); split1(sc[j1][3], h13, l13);
            unsigned pha0 = pack2(h00, h01), pha1 = pack2(h02, h03);
            unsigned pha2 = pack2(h10, h11), pha3 = pack2(h12, h13);
            unsigned pla0 = pack2(l00, l01), pla1 = pack2(l02, l03);
            unsigned pla2 = pack2(l10, l11), pla3 = pack2(l12, l13);

            unsigned vf[8][2];                        // Vh frags
            #pragma unroll
            for (int j = 0; j < 8; j++) {
                unsigned baddr = sbase + OFF_VE +
                    ((16 * kk + (lane & 15)) * AV_STR + 8 * j) * 2;
                ldsm_x2t(baddr, vf[j][0], vf[j][1]);
            }
            #pragma unroll
            for (int j = 0; j < 8; j++)               // Ph * Vh
                mma16816(oa[j][0], oa[j][1], oa[j][2], oa[j][3],
                         pha0, pha1, pha2, pha3, vf[j][0], vf[j][1]);
            #pragma unroll
            for (int j = 0; j < 8; j++)               // Pl * Vh
                mma16816(oa[j][0], oa[j][1], oa[j][2], oa[j][3],
                         pla0, pla1, pla2, pla3, vf[j][0], vf[j][1]);
            #pragma unroll
            for (int j = 0; j < 8; j++) {             // Ph * Vl
                unsigned baddr = sbase + OFF_VE +
                    ((64 + 16 * kk + (lane & 15)) * AV_STR + 8 * j) * 2;
                unsigned b0, b1;
                ldsm_x2t(baddr, b0, b1);
                mma16816(oa[j][0], oa[j][1], oa[j][2], oa[j][3],
                         pha0, pha1, pha2, pha3, b0, b1);
            }
        }
    }

    // ---- epilogue ----
    const float inv0 = 1.0f / l0;
    const float inv1 = 1.0f / l1;
    const int b = bh >> 4;
    const int h = bh & 15;
    const int srow = qb * 128 + r0;
    #pragma unroll
    for (int j = 0; j < 8; j++) {
        int c0 = 8 * j + (lane & 3) * 2;
        float2 v0 = make_float2(oa[j][0] * inv0, oa[j][1] * inv0);
        float2 v1 = make_float2(oa[j][2] * inv1, oa[j][3] * inv1);
        *(float2*)&O[((size_t)b * S_LEN + srow)     * D_DIM + h * DKH + c0] = v0;
        *(float2*)&O[((size_t)b * S_LEN + srow + 8) * D_DIM + h * DKH + c0] = v1;
    }
}

// ---------------------------------------------------------------------------
extern "C" void kernel_launch(void* const* d_in, const int* in_sizes, int n_in,
                              void* d_out, int out_size)
{
    const float* x  = (const float*)d_in[0];
    const float* Wq = (const float*)d_in[1];
    const float* Wk = (const float*)d_in[2];
    const float* Wv = (const float*)d_in[3];
    const float* Wo = (const float*)d_in[4];
    float* out = (float*)d_out;

    cudaFuncSetAttribute(attn_mma_kernel,
                         cudaFuncAttributeMaxDynamicSharedMemorySize, ATT_SMEM);

    float* g_O_ptr = nullptr;
    cudaGetSymbolAddress((void**)&g_O_ptr, g_O);

    dim3 gqkv(M_TOT / 128, N_TOT / 128, 3);
    qkv_kernel<<<gqkv, 256>>>(x, Wq, Wk, Wv);

    dim3 gattn(S_LEN / 128, B_SZ * H_NUM);
    attn_mma_kernel<<<gattn, 256, ATT_SMEM>>>(g_O_ptr);

    dim3 gproj(M_TOT / 128, N_TOT / 128);
    proj_kernel<<<gproj, 256>>>(Wo, out);
}